// round 11
// baseline (speedup 1.0000x reference)
#include <cuda_runtime.h>
#include <math.h>

#define EDGES 65536
#define TE 64
#define NT 256

// ---------------- scaling constants ----------------
#define IS80 0.11180339887498949f   // 1/sqrt(80)
#define IS32 0.17677669529663687f   // 1/sqrt(32)
#define IS3  0.57735026918962576f   // 1/sqrt(3)
#define IS2  0.70710678118654752f   // 1/sqrt(2)
#define SQ3  1.73205080756887729f
#define RBF_STEP (6.0f/127.0f)
#define RBF_COEF (-0.5f/(RBF_STEP*RBF_STEP))
#define ES_STEP  0.4f
#define ES_COEF  (-3.125f)

// ---------------- global scratch ----------------
__device__ float g_Sout[EDGES*16];
__device__ float g_Vout[EDGES*24];
__device__ float g_gs[256];
__device__ float g_gs2[256];
__device__ float g_gv[16];
__device__ float g_gc[16];
__device__ float g_mu[256];
__device__ float g_invs[16];
__device__ float g_invv[16];

// ---------------- shared memory layout (float offsets) ----------------
#define O_SIN 0            // [64][81]  s_in * 1/sqrt(80)
#define O_VIN 5184         // [64][97]  v_in * 1/sqrt(32), layout i*3+c
#define O_VD  11392        // [64][33]  (v_in . Y1) / sqrt(96)
#define O_HT  13504        // [64][68]  h transposed: hT[k][e]
#define O_Y1  17856        // [64][4]
#define O_ES0 18112        // [64][17]
#define O_ACC 19200        // [64][57]: s_conv[24], v_conv[8*3], a2[8]
#define O_W   22848        // [64][128] w_ro chunk      (union w/ RBF)
#define O_RBF 22848        // [64][128] rbf
#define O_WA  31040        // [64][132] Wa chunk
#define O_STAT 39488       // s[256], s2[256], v[16], cnt[16]
#define O_D   40032
#define O_SP  40096
#define O_EB  40160
#define O_II  40224
#define O_JJ  40288
#define SMEM_FLOATS 40352
#define SMEM_BYTES (SMEM_FLOATS*4)

__device__ __forceinline__ float sigmf(float z) { return 1.0f / (1.0f + __expf(-z)); }

// ======================================================================
// Kernel 0: zero global stats
// ======================================================================
__global__ void k_zero() {
    int t = threadIdx.x;
    if (t < 256) { g_gs[t] = 0.f; g_gs2[t] = 0.f; }
    else if (t < 272) g_gv[t-256] = 0.f;
    else if (t < 288) g_gc[t-272] = 0.f;
}

// ======================================================================
// Kernel 1: fused hypernetwork + conv + post projections + stats
// ======================================================================
__global__ __launch_bounds__(NT, 1) void k_main(
    const float* __restrict__ node_fea, const float* __restrict__ edge_attr,
    const int*   __restrict__ edge_index, const int* __restrict__ xs,
    const int*   __restrict__ batch,
    const float* __restrict__ w_rh, const float* __restrict__ b_rh,
    const float* __restrict__ w_ro, const float* __restrict__ b_ro,
    const float* __restrict__ w_pre, const float* __restrict__ b_pre,
    const float* __restrict__ w_sc,
    const float* __restrict__ w_post_s, const float* __restrict__ b_post_s,
    const float* __restrict__ w_post_v)
{
    extern __shared__ float sm[];
    int* smi = (int*)sm;
    const int tid = threadIdx.x;
    const int e0 = blockIdx.x * TE;

    // ---- pass 0+1: zero accumulators/stats, per-edge scalars ----
    for (int i = tid; i < 3648; i += NT) sm[O_ACC + i] = 0.f;
    for (int i = tid; i < 544; i += NT)  sm[O_STAT + i] = 0.f;
    if (tid < TE) {
        int ge = e0 + tid;
        int ii = edge_index[ge], jj = edge_index[EDGES + ge];
        smi[O_II + tid] = ii;
        smi[O_JJ + tid] = jj;
        smi[O_SP + tid] = 4 * xs[ii] + xs[jj];
        smi[O_EB + tid] = batch[ii];
        float d  = edge_attr[ge*4 + 0];
        float vx = edge_attr[ge*4 + 1];
        float vy = edge_attr[ge*4 + 2];
        float vz = edge_attr[ge*4 + 3];
        sm[O_D + tid] = d;
        float n = sqrtf(vx*vx + vy*vy + vz*vz) + 1e-12f;
        float s = SQ3 / n;
        sm[O_Y1 + tid*4 + 0] = vx * s;
        sm[O_Y1 + tid*4 + 1] = vy * s;
        sm[O_Y1 + tid*4 + 2] = vz * s;
    }
    __syncthreads();

    // ---- pass 2: es0, rbf, s_in node parts, v_in ----
    #pragma unroll
    for (int t = 0; t < 4; t++) {          // es0: 64x16
        int idx = tid + NT*t; int e = idx >> 4, k = idx & 15;
        float dd = sm[O_D + e] - ES_STEP * (float)k;
        sm[O_ES0 + e*17 + k] = __expf(ES_COEF * dd * dd);
    }
    #pragma unroll
    for (int t = 0; t < 32; t++) {         // rbf: 64x128
        int idx = tid + NT*t; int e = idx >> 7, b = idx & 127;
        float dd = sm[O_D + e] - RBF_STEP * (float)b;
        sm[O_RBF + e*128 + b] = __expf(RBF_COEF * dd * dd);
    }
    #pragma unroll
    for (int t = 0; t < 16; t++) {         // s_in[0..63]: 64x64
        int idx = tid + NT*t; int e = idx >> 6, c = idx & 63;
        int node = (c < 32) ? smi[O_II + e] : smi[O_JJ + e];
        sm[O_SIN + e*81 + c] = node_fea[node*80 + (c & 31)] * IS80;
    }
    #pragma unroll
    for (int t = 0; t < 24; t++) {         // v_in: 64x96
        int idx = tid + NT*t; int e = idx / 96, q = idx - e*96;
        int node, f;
        if (q < 48) { node = smi[O_II + e]; f = 32 + q; }
        else        { node = smi[O_JJ + e]; f = 32 + q - 48; }
        sm[O_VIN + e*97 + q] = node_fea[node*80 + f] * IS32;
    }
    __syncthreads();

    // ---- pass 3: edge_s -> s_in[64..79], vdot, h ----
    #pragma unroll
    for (int t = 0; t < 4; t++) {          // edge_s: 64x16
        int idx = tid + NT*t; int e = idx >> 4, o = idx & 15;
        float a = __ldg(&b_pre[o]);
        #pragma unroll
        for (int i = 0; i < 16; i++) a += sm[O_ES0 + e*17 + i] * __ldg(&w_pre[i*16 + o]);
        sm[O_SIN + e*81 + 64 + o] = a * IS80;
    }
    #pragma unroll
    for (int t = 0; t < 8; t++) {          // vdot: 64x32
        int idx = tid + NT*t; int e = idx >> 5, i = idx & 31;
        float a = sm[O_VIN + e*97 + i*3 + 0] * sm[O_Y1 + e*4 + 0]
                + sm[O_VIN + e*97 + i*3 + 1] * sm[O_Y1 + e*4 + 1]
                + sm[O_VIN + e*97 + i*3 + 2] * sm[O_Y1 + e*4 + 2];
        sm[O_VD + e*33 + i] = a * IS3;
    }
    {   // h = silu(rbf @ w_rh + b_rh): thread handles (k=tid&63) x 16 edges
        int k = tid & 63, grp = tid >> 6;
        float acc[16];
        #pragma unroll
        for (int t = 0; t < 16; t++) acc[t] = 0.f;
        for (int b = 0; b < 128; b++) {
            float w = __ldg(&w_rh[b*64 + k]);
            #pragma unroll
            for (int t = 0; t < 16; t++)
                acc[t] += sm[O_RBF + (grp + 4*t)*128 + b] * w;
        }
        float bb = __ldg(&b_rh[k]);
        #pragma unroll
        for (int t = 0; t < 16; t++) {
            float z = acc[t] + bb;
            sm[O_HT + k*68 + grp + 4*t] = z * sigmf(z);
        }
    }
    __syncthreads();

    // ---- phase B: 30 chunks of 128 columns ----
    const int le = tid >> 2, sub = tid & 3;
    const int eg = tid >> 4, cg = tid & 15;
    const float yy0 = sm[O_Y1 + le*4 + 0];
    const float yy1 = sm[O_Y1 + le*4 + 1];
    const float yy2 = sm[O_Y1 + le*4 + 2];
    const float4* w_ro4 = (const float4*)w_ro;

    for (int ch = 0; ch < 30; ch++) {
        const int base = ch << 7;
        // stage w_ro chunk: sh_w[k][c], k<64, c<128
        #pragma unroll
        for (int t = 0; t < 8; t++) {
            int fi = tid + NT*t;              // float4 index 0..2047
            int k = fi >> 5, cq = fi & 31;
            ((float4*)(sm + O_W))[fi] = __ldg(&w_ro4[k*960 + (base >> 2) + cq]);
        }
        __syncthreads();

        // GEMM: Wa[64x128] = hT^T[64x64] @ W[64x128], thread tile 4e x 8c
        float a[4][8];
        #pragma unroll
        for (int r = 0; r < 4; r++)
            #pragma unroll
            for (int q = 0; q < 8; q++) a[r][q] = 0.f;
        const float* hp = sm + O_HT + eg*4;
        const float* wp = sm + O_W  + cg*8;
        #pragma unroll 4
        for (int k = 0; k < 64; k++) {
            float4 hv = *(const float4*)(hp + k*68);
            float4 w0 = *(const float4*)(wp + k*128);
            float4 w1 = *(const float4*)(wp + k*128 + 4);
            float hr[4] = {hv.x, hv.y, hv.z, hv.w};
            float wr[8] = {w0.x, w0.y, w0.z, w0.w, w1.x, w1.y, w1.z, w1.w};
            #pragma unroll
            for (int r = 0; r < 4; r++)
                #pragma unroll
                for (int q = 0; q < 8; q++) a[r][q] += hr[r] * wr[q];
        }
        #pragma unroll
        for (int r = 0; r < 4; r++) {
            int row = eg*4 + r;
            #pragma unroll
            for (int q = 0; q < 8; q++)
                sm[O_WA + row*132 + cg*8 + q] = a[r][q] + __ldg(&b_ro[base + cg*8 + q]);
        }
        __syncthreads();

        // fold chunk into per-edge smem accumulators; col ownership col%4==sub
        {
            const float* wap  = sm + O_WA  + le*132;
            float*       accp = sm + O_ACC + le*57;
            if (base < 1920) {                    // w1: s_in -> s_conv
                #pragma unroll
                for (int j = 0; j < 32; j++) {
                    int gc = base + 4*j + sub;
                    int i = gc / 24, o = gc - i*24;
                    accp[o] += sm[O_SIN + le*81 + i] * wap[4*j + sub];
                }
            } else if (base < 2560) {             // w2: s_in -> a2 (vA)
                #pragma unroll
                for (int j = 0; j < 32; j++) {
                    int l = base - 1920 + 4*j + sub;
                    accp[48 + (l & 7)] += sm[O_SIN + le*81 + (l >> 3)] * wap[4*j + sub];
                }
            } else if (base < 2816) {             // w3: v_in -> v_conv
                #pragma unroll
                for (int j = 0; j < 32; j++) {
                    int l = base - 2560 + 4*j + sub;
                    int i = l >> 3, o = l & 7;
                    float w = wap[4*j + sub];
                    accp[24 + o*3 + 0] += sm[O_VIN + le*97 + i*3 + 0] * w;
                    accp[24 + o*3 + 1] += sm[O_VIN + le*97 + i*3 + 1] * w;
                    accp[24 + o*3 + 2] += sm[O_VIN + le*97 + i*3 + 2] * w;
                }
            } else if (base < 3584) {             // w4: vdot -> s_conv
                #pragma unroll
                for (int j = 0; j < 32; j++) {
                    int l = base - 2816 + 4*j + sub;
                    int i = l / 24, o = l - i*24;
                    accp[o] += sm[O_VD + le*33 + i] * wap[4*j + sub];
                }
            } else {                              // w5: cross(v_in,Y1) -> v_conv
                #pragma unroll
                for (int j = 0; j < 32; j++) {
                    int l = base - 3584 + 4*j + sub;
                    int i = l >> 3, o = l & 7;
                    float w = wap[4*j + sub];
                    float vx = sm[O_VIN + le*97 + i*3 + 0];
                    float vy = sm[O_VIN + le*97 + i*3 + 1];
                    float vz = sm[O_VIN + le*97 + i*3 + 2];
                    accp[24 + o*3 + 0] += (vy*yy2 - vz*yy1) * IS2 * w;
                    accp[24 + o*3 + 1] += (vz*yy0 - vx*yy2) * IS2 * w;
                    accp[24 + o*3 + 2] += (vx*yy1 - vy*yy0) * IS2 * w;
                }
            }
        }
        __syncthreads();
    }

    // ---- epilogue stage 1: silu / gating, spre+vpre into WA rows ----
    {
        float* accp = sm + O_ACC + le*57;
        float g0 = sigmf(accp[16 + sub]);
        float g1 = sigmf(accp[20 + sub]);
        float aA0 = accp[48 + sub], aA1 = accp[52 + sub];
        #pragma unroll
        for (int t = 0; t < 4; t++) {
            int o = sub + 4*t;
            float z = accp[o];
            sm[O_WA + le*132 + o] = z * sigmf(z);          // spre
        }
        float yv[3] = {yy0, yy1, yy2};
        #pragma unroll
        for (int idx = 0; idx < 2; idx++) {
            int o = sub + 4*idx;
            float aA = idx ? aA1 : aA0;
            float g  = idx ? g1  : g0;
            #pragma unroll
            for (int c = 0; c < 3; c++) {
                float v = accp[24 + o*3 + c] + aA * yv[c]; // vB+vC + vA
                sm[O_WA + le*132 + 16 + o*3 + c] = v * g;  // vpre (gated)
            }
        }
    }
    __syncthreads();

    // ---- epilogue stage 2: post projections + sc, stats ----
    {
        const int ge = e0 + le;
        int sp = smi[O_SP + le], eb = smi[O_EB + le];
        #pragma unroll
        for (int t = 0; t < 4; t++) {
            int o = sub + 4*t;
            float a = __ldg(&b_post_s[o]);
            #pragma unroll
            for (int i = 0; i < 16; i++)
                a += sm[O_WA + le*132 + i] * __ldg(&w_post_s[i*16 + o]);
            float sc = 0.f;
            #pragma unroll
            for (int i = 0; i < 16; i++)
                sc += sm[O_ES0 + le*17 + i] * __ldg(&w_sc[i*256 + sp*16 + o]);
            a += sc * 0.0625f;
            g_Sout[ge*16 + o] = a;
            atomicAdd(&sm[O_STAT + eb*16 + o], a);
            atomicAdd(&sm[O_STAT + 256 + eb*16 + o], a * a);
        }
        float v2 = 0.f;
        #pragma unroll
        for (int idx = 0; idx < 2; idx++) {
            int o = sub + 4*idx;
            #pragma unroll
            for (int c = 0; c < 3; c++) {
                float v = 0.f;
                #pragma unroll
                for (int i = 0; i < 8; i++)
                    v += sm[O_WA + le*132 + 16 + i*3 + c] * __ldg(&w_post_v[i*8 + o]);
                g_Vout[ge*24 + o*3 + c] = v;
                v2 += v * v;
            }
        }
        atomicAdd(&sm[O_STAT + 512 + eb], v2);
        if (sub == 0) atomicAdd(&sm[O_STAT + 528 + eb], 1.f);
    }
    __syncthreads();
    if (tid < 256) {
        atomicAdd(&g_gs[tid],  sm[O_STAT + tid]);
        atomicAdd(&g_gs2[tid], sm[O_STAT + 256 + tid]);
    }
    if (tid < 16) {
        atomicAdd(&g_gv[tid], sm[O_STAT + 512 + tid]);
        atomicAdd(&g_gc[tid], sm[O_STAT + 528 + tid]);
    }
}

// ======================================================================
// Kernel 2: per-graph mu / inv-rms
// ======================================================================
__global__ void k_stats() {
    __shared__ float sv[256];
    int t = threadIdx.x;
    int g = t >> 4;
    float cnt = fmaxf(g_gc[g], 1.f);
    float mu = g_gs[t] / cnt;
    g_mu[t] = mu;
    sv[t] = g_gs2[t] / cnt - mu * mu;
    __syncthreads();
    if ((t & 15) == 0) {
        float a = 0.f;
        #pragma unroll
        for (int f = 0; f < 16; f++) a += sv[t + f];
        a *= (1.f / 16.f);
        g_invs[g] = 1.f / sqrtf(a + 1e-5f);
        g_invv[g] = 1.f / sqrtf(g_gv[g] / (cnt * 24.f) + 1e-5f);
    }
}

// ======================================================================
// Kernel 3: layernorm + skip + edge projections -> output
// ======================================================================
__global__ __launch_bounds__(256) void k_final(
    const float* __restrict__ edge_attr, const int* __restrict__ edge_index,
    const int*   __restrict__ batch,
    const float* __restrict__ ln_w_s, const float* __restrict__ ln_b_s,
    const float* __restrict__ ln_w_v,
    const float* __restrict__ w_skip, const float* __restrict__ w_edge_s,
    const float* __restrict__ b_edge_s, const float* __restrict__ w_edge_v,
    float* __restrict__ out)
{
    __shared__ float s_skip[256], s_es[256], s_ev[64], s_be[16];
    __shared__ float s_lws[16], s_lbs[16], s_lwv[8], s_mu[256], s_is[16], s_iv[16];
    int tid = threadIdx.x;
    s_skip[tid] = w_skip[tid];
    s_es[tid]   = w_edge_s[tid];
    s_mu[tid]   = g_mu[tid];
    if (tid < 64) s_ev[tid] = w_edge_v[tid];
    if (tid < 16) {
        s_be[tid] = b_edge_s[tid]; s_lws[tid] = ln_w_s[tid]; s_lbs[tid] = ln_b_s[tid];
        s_is[tid] = g_invs[tid];   s_iv[tid] = g_invv[tid];
    }
    if (tid < 8) s_lwv[tid] = ln_w_v[tid];
    __syncthreads();

    int ge = blockIdx.x * 256 + tid;
    int g = batch[edge_index[ge]];
    float d = edge_attr[ge*4];
    float es0[16];
    #pragma unroll
    for (int k = 0; k < 16; k++) {
        float dd = d - ES_STEP * (float)k;
        es0[k] = __expf(ES_COEF * dd * dd);
    }
    float inv_s = s_is[g], inv_v = s_iv[g];
    float sn[16];
    #pragma unroll
    for (int i = 0; i < 16; i++) {
        float sv = g_Sout[ge*16 + i];
        float v = (sv - s_mu[g*16 + i]) * inv_s * s_lws[i] + s_lbs[i];
        float sk = 0.f;
        #pragma unroll
        for (int k = 0; k < 16; k++) sk += es0[k] * s_skip[k*16 + i];
        sn[i] = v + sk;
    }
    #pragma unroll
    for (int o = 0; o < 16; o++) {
        float a = s_be[o];
        #pragma unroll
        for (int i = 0; i < 16; i++) a += sn[i] * s_es[i*16 + o];
        out[ge*40 + o] = a;
    }
    float vn[24];
    #pragma unroll
    for (int i = 0; i < 8; i++) {
        float w = inv_v * s_lwv[i];
        #pragma unroll
        for (int c = 0; c < 3; c++) vn[i*3 + c] = g_Vout[ge*24 + i*3 + c] * w;
    }
    #pragma unroll
    for (int o = 0; o < 8; o++) {
        #pragma unroll
        for (int c = 0; c < 3; c++) {
            float a = 0.f;
            #pragma unroll
            for (int i = 0; i < 8; i++) a += vn[i*3 + c] * s_ev[i*8 + o];
            out[ge*40 + 16 + o*3 + c] = a;
        }
    }
}

// ======================================================================
extern "C" void kernel_launch(void* const* d_in, const int* in_sizes, int n_in,
                              void* d_out, int out_size)
{
    const float* node_fea  = (const float*)d_in[0];
    const float* edge_attr = (const float*)d_in[1];
    const int*   edge_index= (const int*)  d_in[2];
    const int*   xs        = (const int*)  d_in[3];
    const int*   batch     = (const int*)  d_in[4];
    const float* w_rh      = (const float*)d_in[5];
    const float* b_rh      = (const float*)d_in[6];
    const float* w_ro      = (const float*)d_in[7];
    const float* b_ro      = (const float*)d_in[8];
    const float* w_pre     = (const float*)d_in[9];
    const float* b_pre     = (const float*)d_in[10];
    const float* w_sc      = (const float*)d_in[11];
    const float* w_post_s  = (const float*)d_in[12];
    const float* b_post_s  = (const float*)d_in[13];
    const float* w_post_v  = (const float*)d_in[14];
    const float* ln_w_s    = (const float*)d_in[15];
    const float* ln_b_s    = (const float*)d_in[16];
    const float* ln_w_v    = (const float*)d_in[17];
    const float* w_skip    = (const float*)d_in[18];
    const float* w_edge_s  = (const float*)d_in[19];
    const float* b_edge_s  = (const float*)d_in[20];
    const float* w_edge_v  = (const float*)d_in[21];
    float* out = (float*)d_out;

    cudaFuncSetAttribute(k_main, cudaFuncAttributeMaxDynamicSharedMemorySize, SMEM_BYTES);

    k_zero<<<1, 288>>>();
    k_main<<<EDGES/TE, NT, SMEM_BYTES>>>(
        node_fea, edge_attr, edge_index, xs, batch,
        w_rh, b_rh, w_ro, b_ro, w_pre, b_pre, w_sc,
        w_post_s, b_post_s, w_post_v);
    k_stats<<<1, 256>>>();
    k_final<<<EDGES/256, 256>>>(
        edge_attr, edge_index, batch,
        ln_w_s, ln_b_s, ln_w_v, w_skip, w_edge_s, b_edge_s, w_edge_v, out);
}

// round 12
// speedup vs baseline: 2.1231x; 2.1231x over previous
#include <cuda_runtime.h>
#include <math.h>

#define EDGES 65536
#define TE 64
#define NT 256

// ---------------- scaling constants ----------------
#define IS80 0.11180339887498949f   // 1/sqrt(80)
#define IS32 0.17677669529663687f   // 1/sqrt(32)
#define IS3  0.57735026918962576f   // 1/sqrt(3)
#define IS2  0.70710678118654752f   // 1/sqrt(2)
#define SQ3  1.73205080756887729f
#define RBF_STEP (6.0f/127.0f)
#define RBF_COEF (-0.5f/(RBF_STEP*RBF_STEP))
#define ES_STEP  0.4f
#define ES_COEF  (-3.125f)

// ---------------- global scratch ----------------
__device__ float g_Sout[EDGES*16];
__device__ float g_Vout[EDGES*24];
__device__ float g_gs[256];
__device__ float g_gs2[256];
__device__ float g_gv[16];
__device__ float g_gc[16];
__device__ float g_mu[256];
__device__ float g_invs[16];
__device__ float g_invv[16];

// ---------------- shared memory layout (float offsets) ----------------
#define O_SIN 0            // [64][81]  s_in * 1/sqrt(80)
#define O_VIN 5184         // [64][97]  v_in * 1/sqrt(32), layout i*3+c
#define O_VD  11392        // [64][33]  (v_in . Y1) / sqrt(96)
#define O_HT2 13504        // [64 k][132] h duplicated: [k][2e]=[k][2e+1]=h[e][k]
#define O_Y1  21952        // [64][4]
#define O_ES0 22208        // [64][17]
#define O_W0  23296        // [64][128] w_ro chunk buf 0
#define O_W1  31488        // [64][128] w_ro chunk buf 1 (alias: w_rh staging [128][64])
#define O_WA  39680        // [64][132] Wa chunk (alias: RBF [64][132] in prologue)
#define O_RBF O_WA
#define O_PRE 48128        // [64][41]  spre[16] + vpre[24]
#define O_STAT 50752       // s[256], s2[256], v[16], cnt[16]
#define O_D   51296
#define O_SP  51360
#define O_EB  51424
#define O_II  51488
#define O_JJ  51552
#define SMEM_FLOATS 51616
#define SMEM_BYTES (SMEM_FLOATS*4)
#define O_ACCD O_W0        // [64][57] epilogue acc dump (W buffers dead after loop)

__device__ __forceinline__ float sigmf(float z) { return 1.0f / (1.0f + __expf(-z)); }

// packed fp32x2 FMA (bit-exact: two IEEE fp32 FMAs)
#define FMA2(d, a, b) asm("fma.rn.f32x2 %0, %1, %2, %0;" : "+l"(d) : "l"(a), "l"(b))
#define UNPACK2(lo, hi, v) asm("mov.b64 {%0, %1}, %2;" : "=f"(lo), "=f"(hi) : "l"(v))

#define CPA16(dst_u32, src_ptr) \
    asm volatile("cp.async.cg.shared.global [%0], [%1], 16;" :: "r"(dst_u32), "l"(src_ptr))
#define CP_COMMIT() asm volatile("cp.async.commit_group;")
#define CP_WAIT1()  asm volatile("cp.async.wait_group 1;")
#define CP_WAIT0()  asm volatile("cp.async.wait_group 0;")

// ======================================================================
// Kernel 0: zero global stats
// ======================================================================
__global__ void k_zero() {
    int t = threadIdx.x;
    if (t < 256) { g_gs[t] = 0.f; g_gs2[t] = 0.f; }
    else if (t < 272) g_gv[t-256] = 0.f;
    else if (t < 288) g_gc[t-272] = 0.f;
}

// ======================================================================
// Kernel 1: fused hypernetwork + conv + post projections + stats
// ======================================================================
__global__ __launch_bounds__(NT, 1) void k_main(
    const float* __restrict__ node_fea, const float* __restrict__ edge_attr,
    const int*   __restrict__ edge_index, const int* __restrict__ xs,
    const int*   __restrict__ batch,
    const float* __restrict__ w_rh, const float* __restrict__ b_rh,
    const float* __restrict__ w_ro, const float* __restrict__ b_ro,
    const float* __restrict__ w_pre, const float* __restrict__ b_pre,
    const float* __restrict__ w_sc,
    const float* __restrict__ w_post_s, const float* __restrict__ b_post_s,
    const float* __restrict__ w_post_v)
{
    extern __shared__ float sm[];
    int* smi = (int*)sm;
    const int tid = threadIdx.x;
    const int e0 = blockIdx.x * TE;

    const unsigned w0sa = (unsigned)__cvta_generic_to_shared(sm + O_W0);
    const unsigned w1sa = (unsigned)__cvta_generic_to_shared(sm + O_W1);

    // ---- prefetch: w_rh (group 0) then w_ro chunk 0 (group 1) ----
    #pragma unroll
    for (int q = 0; q < 8; q++) {                  // w_rh: 8192 floats contiguous
        int fi = tid + NT*q;
        CPA16(w1sa + fi*16, w_rh + fi*4);
    }
    CP_COMMIT();
    #pragma unroll
    for (int q = 0; q < 8; q++) {                  // chunk 0
        int fi = tid + NT*q; int k = fi >> 5, c4 = fi & 31;
        CPA16(w0sa + (k*128 + c4*4)*4, w_ro + k*3840 + c4*4);
    }
    CP_COMMIT();

    // ---- per-edge scalars + zero stats ----
    for (int i = tid; i < 544; i += NT) sm[O_STAT + i] = 0.f;
    if (tid < TE) {
        int ge = e0 + tid;
        int ii = edge_index[ge], jj = edge_index[EDGES + ge];
        smi[O_II + tid] = ii;
        smi[O_JJ + tid] = jj;
        smi[O_SP + tid] = 4 * xs[ii] + xs[jj];
        smi[O_EB + tid] = batch[ii];
        float d  = edge_attr[ge*4 + 0];
        float vx = edge_attr[ge*4 + 1];
        float vy = edge_attr[ge*4 + 2];
        float vz = edge_attr[ge*4 + 3];
        sm[O_D + tid] = d;
        float n = sqrtf(vx*vx + vy*vy + vz*vz) + 1e-12f;
        float s = SQ3 / n;
        sm[O_Y1 + tid*4 + 0] = vx * s;
        sm[O_Y1 + tid*4 + 1] = vy * s;
        sm[O_Y1 + tid*4 + 2] = vz * s;
    }
    __syncthreads();

    // ---- pass 2: es0, rbf (into O_RBF alias), s_in node parts, v_in ----
    #pragma unroll
    for (int t = 0; t < 4; t++) {          // es0: 64x16
        int idx = tid + NT*t; int e = idx >> 4, k = idx & 15;
        float dd = sm[O_D + e] - ES_STEP * (float)k;
        sm[O_ES0 + e*17 + k] = __expf(ES_COEF * dd * dd);
    }
    #pragma unroll
    for (int t = 0; t < 32; t++) {         // rbf: 64x128 (stride 132)
        int idx = tid + NT*t; int e = idx >> 7, b = idx & 127;
        float dd = sm[O_D + e] - RBF_STEP * (float)b;
        sm[O_RBF + e*132 + b] = __expf(RBF_COEF * dd * dd);
    }
    #pragma unroll
    for (int t = 0; t < 16; t++) {         // s_in[0..63]: 64x64
        int idx = tid + NT*t; int e = idx >> 6, c = idx & 63;
        int node = (c < 32) ? smi[O_II + e] : smi[O_JJ + e];
        sm[O_SIN + e*81 + c] = node_fea[node*80 + (c & 31)] * IS80;
    }
    #pragma unroll
    for (int t = 0; t < 24; t++) {         // v_in: 64x96
        int idx = tid + NT*t; int e = idx / 96, q = idx - e*96;
        int node, f;
        if (q < 48) { node = smi[O_II + e]; f = 32 + q; }
        else        { node = smi[O_JJ + e]; f = 32 + q - 48; }
        sm[O_VIN + e*97 + q] = node_fea[node*80 + f] * IS32;
    }
    __syncthreads();

    // ---- pass 3: edge_s -> s_in[64..79], vdot ----
    #pragma unroll
    for (int t = 0; t < 4; t++) {          // edge_s: 64x16
        int idx = tid + NT*t; int e = idx >> 4, o = idx & 15;
        float a = __ldg(&b_pre[o]);
        #pragma unroll
        for (int i = 0; i < 16; i++) a += sm[O_ES0 + e*17 + i] * __ldg(&w_pre[i*16 + o]);
        sm[O_SIN + e*81 + 64 + o] = a * IS80;
    }
    #pragma unroll
    for (int t = 0; t < 8; t++) {          // vdot: 64x32
        int idx = tid + NT*t; int e = idx >> 5, i = idx & 31;
        float a = sm[O_VIN + e*97 + i*3 + 0] * sm[O_Y1 + e*4 + 0]
                + sm[O_VIN + e*97 + i*3 + 1] * sm[O_Y1 + e*4 + 1]
                + sm[O_VIN + e*97 + i*3 + 2] * sm[O_Y1 + e*4 + 2];
        sm[O_VD + e*33 + i] = a * IS3;
    }
    CP_WAIT1();            // w_rh staged (chunk0 may still fly)
    __syncthreads();

    // ---- h-GEMM: h[64e][64k] = silu(rbf[64x128] @ w_rh[128x64] + b) -> HT2 dup ----
    {
        const int eg2 = tid >> 4;   // edges 4*eg2..+3
        const int kg  = tid & 15;   // ks    4*kg ..+3
        float c[4][4];              // [kk][r]
        #pragma unroll
        for (int kk = 0; kk < 4; kk++)
            #pragma unroll
            for (int r = 0; r < 4; r++) c[kk][r] = 0.f;
        const float* rp = sm + O_RBF + eg2*4*132;
        const float* wp = sm + O_W1 + kg*4;
        #pragma unroll 2
        for (int b = 0; b < 128; b++) {
            float4 wv = *(const float4*)(wp + b*64);
            float wr[4] = {wv.x, wv.y, wv.z, wv.w};
            float rv[4];
            #pragma unroll
            for (int r = 0; r < 4; r++) rv[r] = rp[r*132 + b];
            #pragma unroll
            for (int kk = 0; kk < 4; kk++)
                #pragma unroll
                for (int r = 0; r < 4; r++) c[kk][r] += wr[kk] * rv[r];
        }
        #pragma unroll
        for (int kk = 0; kk < 4; kk++) {
            int k = 4*kg + kk;
            float bb = __ldg(&b_rh[k]);
            #pragma unroll
            for (int r = 0; r < 4; r++) {
                float z = c[kk][r] + bb;
                float h = z * sigmf(z);
                int e = 4*eg2 + r;
                sm[O_HT2 + k*132 + 2*e]     = h;
                sm[O_HT2 + k*132 + 2*e + 1] = h;
            }
        }
    }
    __syncthreads();

    // ---- phase B: 30 chunks of 128 columns, f32x2 GEMM + register fold ----
    const int eg = tid >> 4, cg = tid & 15;
    const int le = tid >> 2, sub = tid & 3;
    const float yy0 = sm[O_Y1 + le*4 + 0];
    const float yy1 = sm[O_Y1 + le*4 + 1];
    const float yy2 = sm[O_Y1 + le*4 + 2];

    float acS[6], acV[2][3], acA[2];
    #pragma unroll
    for (int r = 0; r < 6; r++) acS[r] = 0.f;
    #pragma unroll
    for (int r = 0; r < 2; r++) { acA[r] = 0.f; acV[r][0] = acV[r][1] = acV[r][2] = 0.f; }

    for (int ch = 0; ch < 30; ch++) {
        const int base = ch << 7;
        if (ch < 29) {                      // prefetch chunk ch+1
            const int nbase = base + 128;
            const unsigned dsa = ((ch + 1) & 1) ? w1sa : w0sa;
            #pragma unroll
            for (int q = 0; q < 8; q++) {
                int fi = tid + NT*q; int k = fi >> 5, c4 = fi & 31;
                CPA16(dsa + (k*128 + c4*4)*4, w_ro + k*3840 + nbase + c4*4);
            }
            CP_COMMIT();
            CP_WAIT1();
        } else {
            CP_WAIT0();
        }
        __syncthreads();

        // GEMM: Wa[64x128] = hT^T @ W, thread tile 4 edges x 8 cols (4 col-pairs)
        const float* wb = sm + ((ch & 1) ? O_W1 : O_W0);
        unsigned long long acc[4][4];
        #pragma unroll
        for (int r = 0; r < 4; r++)
            #pragma unroll
            for (int p = 0; p < 4; p++) acc[r][p] = 0ull;
        const float* hp  = sm + O_HT2 + eg*8;
        const float* wp0 = wb + cg*4;
        #pragma unroll 4
        for (int k = 0; k < 64; k++) {
            ulonglong2 hv  = *(const ulonglong2*)(hp + k*132);      // (h0,h0),(h1,h1)
            ulonglong2 hv2 = *(const ulonglong2*)(hp + k*132 + 4);  // (h2,h2),(h3,h3)
            ulonglong2 wv  = *(const ulonglong2*)(wp0 + k*128);     // pairs at cg*4
            ulonglong2 wv2 = *(const ulonglong2*)(wp0 + k*128 + 64);// pairs at 64+cg*4
            FMA2(acc[0][0], hv.x,  wv.x);  FMA2(acc[0][1], hv.x,  wv.y);
            FMA2(acc[0][2], hv.x,  wv2.x); FMA2(acc[0][3], hv.x,  wv2.y);
            FMA2(acc[1][0], hv.y,  wv.x);  FMA2(acc[1][1], hv.y,  wv.y);
            FMA2(acc[1][2], hv.y,  wv2.x); FMA2(acc[1][3], hv.y,  wv2.y);
            FMA2(acc[2][0], hv2.x, wv.x);  FMA2(acc[2][1], hv2.x, wv.y);
            FMA2(acc[2][2], hv2.x, wv2.x); FMA2(acc[2][3], hv2.x, wv2.y);
            FMA2(acc[3][0], hv2.y, wv.x);  FMA2(acc[3][1], hv2.y, wv.y);
            FMA2(acc[3][2], hv2.y, wv2.x); FMA2(acc[3][3], hv2.y, wv2.y);
        }
        #pragma unroll
        for (int r = 0; r < 4; r++) {
            int row = 4*eg + r;
            #pragma unroll
            for (int p = 0; p < 4; p++) {
                int pc = (p < 2) ? (cg*4 + 2*p) : (64 + cg*4 + 2*(p-2));
                float lo, hi;
                UNPACK2(lo, hi, acc[r][p]);
                sm[O_WA + row*132 + pc]     = lo + __ldg(&b_ro[base + pc]);
                sm[O_WA + row*132 + pc + 1] = hi + __ldg(&b_ro[base + pc + 1]);
            }
        }
        __syncthreads();

        // fold chunk into register accumulators
        const float* wap = sm + O_WA + le*132;
        if (base < 1920) {                         // w1: s_in -> s_conv
            #pragma unroll
            for (int r = 0; r < 6; r++) {
                int q = 6*sub + r;
                int m    = (base - q + 23) / 24;
                int mend = (base + 151 - q) / 24;
                #pragma unroll 1
                for (; m < mend; m++)
                    acS[r] += sm[O_SIN + le*81 + m] * wap[24*m + q - base];
            }
        } else if (base < 2560) {                  // w2: s_in -> a2 (vA)
            int i0 = (base - 1920) >> 3;
            #pragma unroll
            for (int r = 0; r < 2; r++) {
                int q = 2*sub + r;
                #pragma unroll
                for (int mm = 0; mm < 16; mm++)
                    acA[r] += sm[O_SIN + le*81 + i0 + mm] * wap[8*mm + q];
            }
        } else if (base < 2816) {                  // w3: v_in -> v_conv
            int i0 = (base - 2560) >> 3;
            #pragma unroll
            for (int r = 0; r < 2; r++) {
                int q = 2*sub + r;
                #pragma unroll
                for (int mm = 0; mm < 16; mm++) {
                    int i = i0 + mm;
                    float w = wap[8*mm + q];
                    acV[r][0] += sm[O_VIN + le*97 + 3*i + 0] * w;
                    acV[r][1] += sm[O_VIN + le*97 + 3*i + 1] * w;
                    acV[r][2] += sm[O_VIN + le*97 + 3*i + 2] * w;
                }
            }
        } else if (base < 3584) {                  // w4: vdot -> s_conv
            int gs0 = base - 2816;
            #pragma unroll
            for (int r = 0; r < 6; r++) {
                int q = 6*sub + r;
                int m    = (gs0 - q + 23) / 24;
                int mend = (gs0 + 151 - q) / 24;
                #pragma unroll 1
                for (; m < mend; m++)
                    acS[r] += sm[O_VD + le*33 + m] * wap[24*m + q - gs0];
            }
        } else {                                   // w5: cross(v_in,Y1) -> v_conv
            int i0 = (base - 3584) >> 3;
            #pragma unroll
            for (int r = 0; r < 2; r++) {
                int q = 2*sub + r;
                #pragma unroll
                for (int mm = 0; mm < 16; mm++) {
                    int i = i0 + mm;
                    float w = wap[8*mm + q] * IS2;
                    float vx = sm[O_VIN + le*97 + 3*i + 0];
                    float vy = sm[O_VIN + le*97 + 3*i + 1];
                    float vz = sm[O_VIN + le*97 + 3*i + 2];
                    acV[r][0] += (vy*yy2 - vz*yy1) * w;
                    acV[r][1] += (vz*yy0 - vx*yy2) * w;
                    acV[r][2] += (vx*yy1 - vy*yy0) * w;
                }
            }
        }
        // no sync needed: next-iter top sync separates fold reads from WA writes
    }

    // ---- dump register accumulators to smem (alias over dead W buffer 0) ----
    {
        float* accd = sm + O_ACCD + le*57;
        #pragma unroll
        for (int r = 0; r < 6; r++) accd[6*sub + r] = acS[r];
        #pragma unroll
        for (int r = 0; r < 2; r++) {
            accd[24 + (2*sub + r)*3 + 0] = acV[r][0];
            accd[24 + (2*sub + r)*3 + 1] = acV[r][1];
            accd[24 + (2*sub + r)*3 + 2] = acV[r][2];
            accd[48 + 2*sub + r] = acA[r];
        }
    }
    __syncthreads();

    // ---- epilogue stage 1: silu / gating, spre+vpre into PRE rows ----
    {
        const float* accp = sm + O_ACCD + le*57;
        float g0 = sigmf(accp[16 + sub]);
        float g1 = sigmf(accp[20 + sub]);
        float aA0 = accp[48 + sub], aA1 = accp[52 + sub];
        #pragma unroll
        for (int t = 0; t < 4; t++) {
            int o = sub + 4*t;
            float z = accp[o];
            sm[O_PRE + le*41 + o] = z * sigmf(z);              // spre
        }
        float yv[3] = {yy0, yy1, yy2};
        #pragma unroll
        for (int idx = 0; idx < 2; idx++) {
            int o = sub + 4*idx;
            float aA = idx ? aA1 : aA0;
            float g  = idx ? g1  : g0;
            #pragma unroll
            for (int c = 0; c < 3; c++) {
                float v = accp[24 + o*3 + c] + aA * yv[c];     // vB+vC + vA
                sm[O_PRE + le*41 + 16 + o*3 + c] = v * g;      // vpre (gated)
            }
        }
    }
    __syncthreads();

    // ---- epilogue stage 2: post projections + sc, stats ----
    {
        const int ge = e0 + le;
        int sp = smi[O_SP + le], eb = smi[O_EB + le];
        #pragma unroll
        for (int t = 0; t < 4; t++) {
            int o = sub + 4*t;
            float a = __ldg(&b_post_s[o]);
            #pragma unroll
            for (int i = 0; i < 16; i++)
                a += sm[O_PRE + le*41 + i] * __ldg(&w_post_s[i*16 + o]);
            float sc = 0.f;
            #pragma unroll
            for (int i = 0; i < 16; i++)
                sc += sm[O_ES0 + le*17 + i] * __ldg(&w_sc[i*256 + sp*16 + o]);
            a += sc * 0.0625f;
            g_Sout[ge*16 + o] = a;
            atomicAdd(&sm[O_STAT + eb*16 + o], a);
            atomicAdd(&sm[O_STAT + 256 + eb*16 + o], a * a);
        }
        float v2 = 0.f;
        #pragma unroll
        for (int idx = 0; idx < 2; idx++) {
            int o = sub + 4*idx;
            #pragma unroll
            for (int c = 0; c < 3; c++) {
                float v = 0.f;
                #pragma unroll
                for (int i = 0; i < 8; i++)
                    v += sm[O_PRE + le*41 + 16 + i*3 + c] * __ldg(&w_post_v[i*8 + o]);
                g_Vout[ge*24 + o*3 + c] = v;
                v2 += v * v;
            }
        }
        atomicAdd(&sm[O_STAT + 512 + eb], v2);
        if (sub == 0) atomicAdd(&sm[O_STAT + 528 + eb], 1.f);
    }
    __syncthreads();
    if (tid < 256) {
        atomicAdd(&g_gs[tid],  sm[O_STAT + tid]);
        atomicAdd(&g_gs2[tid], sm[O_STAT + 256 + tid]);
    }
    if (tid < 16) {
        atomicAdd(&g_gv[tid], sm[O_STAT + 512 + tid]);
        atomicAdd(&g_gc[tid], sm[O_STAT + 528 + tid]);
    }
}

// ======================================================================
// Kernel 2: per-graph mu / inv-rms
// ======================================================================
__global__ void k_stats() {
    __shared__ float sv[256];
    int t = threadIdx.x;
    int g = t >> 4;
    float cnt = fmaxf(g_gc[g], 1.f);
    float mu = g_gs[t] / cnt;
    g_mu[t] = mu;
    sv[t] = g_gs2[t] / cnt - mu * mu;
    __syncthreads();
    if ((t & 15) == 0) {
        float a = 0.f;
        #pragma unroll
        for (int f = 0; f < 16; f++) a += sv[t + f];
        a *= (1.f / 16.f);
        g_invs[g] = 1.f / sqrtf(a + 1e-5f);
        g_invv[g] = 1.f / sqrtf(g_gv[g] / (cnt * 24.f) + 1e-5f);
    }
}

// ======================================================================
// Kernel 3: layernorm + skip + edge projections -> output
// ======================================================================
__global__ __launch_bounds__(256) void k_final(
    const float* __restrict__ edge_attr, const int* __restrict__ edge_index,
    const int*   __restrict__ batch,
    const float* __restrict__ ln_w_s, const float* __restrict__ ln_b_s,
    const float* __restrict__ ln_w_v,
    const float* __restrict__ w_skip, const float* __restrict__ w_edge_s,
    const float* __restrict__ b_edge_s, const float* __restrict__ w_edge_v,
    float* __restrict__ out)
{
    __shared__ float s_skip[256], s_es[256], s_ev[64], s_be[16];
    __shared__ float s_lws[16], s_lbs[16], s_lwv[8], s_mu[256], s_is[16], s_iv[16];
    int tid = threadIdx.x;
    s_skip[tid] = w_skip[tid];
    s_es[tid]   = w_edge_s[tid];
    s_mu[tid]   = g_mu[tid];
    if (tid < 64) s_ev[tid] = w_edge_v[tid];
    if (tid < 16) {
        s_be[tid] = b_edge_s[tid]; s_lws[tid] = ln_w_s[tid]; s_lbs[tid] = ln_b_s[tid];
        s_is[tid] = g_invs[tid];   s_iv[tid] = g_invv[tid];
    }
    if (tid < 8) s_lwv[tid] = ln_w_v[tid];
    __syncthreads();

    int ge = blockIdx.x * 256 + tid;
    int g = batch[edge_index[ge]];
    float d = edge_attr[ge*4];
    float es0[16];
    #pragma unroll
    for (int k = 0; k < 16; k++) {
        float dd = d - ES_STEP * (float)k;
        es0[k] = __expf(ES_COEF * dd * dd);
    }
    float inv_s = s_is[g], inv_v = s_iv[g];
    float sn[16];
    #pragma unroll
    for (int i = 0; i < 16; i++) {
        float sv = g_Sout[ge*16 + i];
        float v = (sv - s_mu[g*16 + i]) * inv_s * s_lws[i] + s_lbs[i];
        float sk = 0.f;
        #pragma unroll
        for (int k = 0; k < 16; k++) sk += es0[k] * s_skip[k*16 + i];
        sn[i] = v + sk;
    }
    #pragma unroll
    for (int o = 0; o < 16; o++) {
        float a = s_be[o];
        #pragma unroll
        for (int i = 0; i < 16; i++) a += sn[i] * s_es[i*16 + o];
        out[ge*40 + o] = a;
    }
    float vn[24];
    #pragma unroll
    for (int i = 0; i < 8; i++) {
        float w = inv_v * s_lwv[i];
        #pragma unroll
        for (int c = 0; c < 3; c++) vn[i*3 + c] = g_Vout[ge*24 + i*3 + c] * w;
    }
    #pragma unroll
    for (int o = 0; o < 8; o++) {
        #pragma unroll
        for (int c = 0; c < 3; c++) {
            float a = 0.f;
            #pragma unroll
            for (int i = 0; i < 8; i++) a += vn[i*3 + c] * s_ev[i*8 + o];
            out[ge*40 + 16 + o*3 + c] = a;
        }
    }
}

// ======================================================================
extern "C" void kernel_launch(void* const* d_in, const int* in_sizes, int n_in,
                              void* d_out, int out_size)
{
    const float* node_fea  = (const float*)d_in[0];
    const float* edge_attr = (const float*)d_in[1];
    const int*   edge_index= (const int*)  d_in[2];
    const int*   xs        = (const int*)  d_in[3];
    const int*   batch     = (const int*)  d_in[4];
    const float* w_rh      = (const float*)d_in[5];
    const float* b_rh      = (const float*)d_in[6];
    const float* w_ro      = (const float*)d_in[7];
    const float* b_ro      = (const float*)d_in[8];
    const float* w_pre     = (const float*)d_in[9];
    const float* b_pre     = (const float*)d_in[10];
    const float* w_sc      = (const float*)d_in[11];
    const float* w_post_s  = (const float*)d_in[12];
    const float* b_post_s  = (const float*)d_in[13];
    const float* w_post_v  = (const float*)d_in[14];
    const float* ln_w_s    = (const float*)d_in[15];
    const float* ln_b_s    = (const float*)d_in[16];
    const float* ln_w_v    = (const float*)d_in[17];
    const float* w_skip    = (const float*)d_in[18];
    const float* w_edge_s  = (const float*)d_in[19];
    const float* b_edge_s  = (const float*)d_in[20];
    const float* w_edge_v  = (const float*)d_in[21];
    float* out = (float*)d_out;

    cudaFuncSetAttribute(k_main, cudaFuncAttributeMaxDynamicSharedMemorySize, SMEM_BYTES);

    k_zero<<<1, 288>>>();
    k_main<<<EDGES/TE, NT, SMEM_BYTES>>>(
        node_fea, edge_attr, edge_index, xs, batch,
        w_rh, b_rh, w_ro, b_ro, w_pre, b_pre, w_sc,
        w_post_s, b_post_s, w_post_v);
    k_stats<<<1, 256>>>();
    k_final<<<EDGES/256, 256>>>(
        edge_attr, edge_index, batch,
        ln_w_s, ln_b_s, ln_w_v, w_skip, w_edge_s, b_edge_s, w_edge_v, out);
}

// round 13
// speedup vs baseline: 2.5768x; 1.2137x over previous
#include <cuda_runtime.h>
#include <math.h>

#define EDGES 65536
#define TE 64
#define NT 256

// ---------------- scaling constants ----------------
#define IS80 0.11180339887498949f   // 1/sqrt(80)
#define IS32 0.17677669529663687f   // 1/sqrt(32)
#define IS3  0.57735026918962576f   // 1/sqrt(3)
#define IS2  0.70710678118654752f   // 1/sqrt(2)
#define SQ3  1.73205080756887729f
#define RBF_STEP (6.0f/127.0f)
#define RBF_COEF (-0.5f/(RBF_STEP*RBF_STEP))
#define ES_STEP  0.4f
#define ES_COEF  (-3.125f)

// ---------------- global scratch ----------------
__device__ float g_Sout[EDGES*16];
__device__ float g_Vout[EDGES*24];
__device__ float g_gs[256];
__device__ float g_gs2[256];
__device__ float g_gv[16];
__device__ float g_gc[16];
__device__ float g_mu[256];
__device__ float g_invs[16];
__device__ float g_invv[16];

// ---------------- shared memory layout (float offsets) ----------------
#define O_SIN 0            // [64][81]  s_in * 1/sqrt(80)
#define O_VIN 5184         // [64][97]  v_in * 1/sqrt(32), layout i*3+c
#define O_VD  11392        // [64][33]  (v_in . Y1) / sqrt(96)
#define O_HT  13504        // [65 k][66] h transposed: HT[k][e]; row 64 = 1.0
#define O_Y1  17794        // [64][4]
#define O_ES0 18050        // [64][17]
#define O_W0  19140        // [65][128] w_ro chunk buf 0 (row 64 = b_ro slice)
#define O_W1  27460        // [65][128] buf 1 (alias: w_rh staging [128][64])
#define O_WA  35780        // [64][132] Wa chunk (alias: RBF in prologue)
#define O_RBF O_WA
#define O_PRE 44228        // [64][41]  spre[16] + vpre[24]
#define O_STAT 46852       // s[256], s2[256], v[16], cnt[16]
#define O_D   47396
#define O_SP  47460
#define O_EB  47524
#define O_II  47588
#define O_JJ  47652
#define SMEM_FLOATS 47716
#define SMEM_BYTES (SMEM_FLOATS*4)
#define O_ACCD O_W0        // [64][57] epilogue acc dump (W buffers dead after loop)

__device__ __forceinline__ float sigmf(float z) { return 1.0f / (1.0f + __expf(-z)); }

// packed fp32x2 FMA (bit-exact: two IEEE fp32 FMAs)
#define FMA2(d, a, b) asm("fma.rn.f32x2 %0, %1, %2, %0;" : "+l"(d) : "l"(a), "l"(b))
#define PACKDUP(d, x) asm("mov.b64 %0, {%1, %1};" : "=l"(d) : "f"(x))

#define CPA16(dst_u32, src_ptr) \
    asm volatile("cp.async.cg.shared.global [%0], [%1], 16;" :: "r"(dst_u32), "l"(src_ptr))
#define CP_COMMIT() asm volatile("cp.async.commit_group;")
#define CP_WAIT1()  asm volatile("cp.async.wait_group 1;")
#define CP_WAIT0()  asm volatile("cp.async.wait_group 0;")

// fold helper: s-type chunk (period-24 blocks), RR0 = (base%24)/4 compile-time
template<int RR0>
__device__ __forceinline__ void foldS(float acS[6], const float* __restrict__ src,
                                      const float* __restrict__ wap, int sub) {
    #pragma unroll
    for (int j = 0; j < 32; j++) {
        const int rr = (RR0 + j) % 6;
        const int di = (RR0 + j) / 6;
        acS[rr] += src[di] * wap[4*j + sub];
    }
}

// ======================================================================
// Kernel 0: zero global stats
// ======================================================================
__global__ void k_zero() {
    int t = threadIdx.x;
    if (t < 256) { g_gs[t] = 0.f; g_gs2[t] = 0.f; }
    else if (t < 272) g_gv[t-256] = 0.f;
    else if (t < 288) g_gc[t-272] = 0.f;
}

// ======================================================================
// Kernel 1: fused hypernetwork + conv + post projections + stats
// ======================================================================
__global__ __launch_bounds__(NT, 1) void k_main(
    const float* __restrict__ node_fea, const float* __restrict__ edge_attr,
    const int*   __restrict__ edge_index, const int* __restrict__ xs,
    const int*   __restrict__ batch,
    const float* __restrict__ w_rh, const float* __restrict__ b_rh,
    const float* __restrict__ w_ro, const float* __restrict__ b_ro,
    const float* __restrict__ w_pre, const float* __restrict__ b_pre,
    const float* __restrict__ w_sc,
    const float* __restrict__ w_post_s, const float* __restrict__ b_post_s,
    const float* __restrict__ w_post_v)
{
    extern __shared__ float sm[];
    int* smi = (int*)sm;
    const int tid = threadIdx.x;
    const int e0 = blockIdx.x * TE;

    const unsigned w0sa = (unsigned)__cvta_generic_to_shared(sm + O_W0);
    const unsigned w1sa = (unsigned)__cvta_generic_to_shared(sm + O_W1);

    // ---- prefetch: w_rh (group 0) then w_ro chunk 0 + bias row (group 1) ----
    #pragma unroll
    for (int q = 0; q < 8; q++) {                  // w_rh: 8192 floats contiguous
        int fi = tid + NT*q;
        CPA16(w1sa + fi*16, w_rh + fi*4);
    }
    CP_COMMIT();
    #pragma unroll
    for (int q = 0; q < 8; q++) {                  // chunk 0
        int fi = tid + NT*q; int k = fi >> 5, c4 = fi & 31;
        CPA16(w0sa + (k*128 + c4*4)*4, w_ro + k*3840 + c4*4);
    }
    if (tid < 32) CPA16(w0sa + (64*128 + tid*4)*4, b_ro + tid*4);
    CP_COMMIT();

    // ---- per-edge scalars + zero stats ----
    for (int i = tid; i < 544; i += NT) sm[O_STAT + i] = 0.f;
    if (tid < TE) {
        int ge = e0 + tid;
        int ii = edge_index[ge], jj = edge_index[EDGES + ge];
        smi[O_II + tid] = ii;
        smi[O_JJ + tid] = jj;
        smi[O_SP + tid] = 4 * xs[ii] + xs[jj];
        smi[O_EB + tid] = batch[ii];
        float d  = edge_attr[ge*4 + 0];
        float vx = edge_attr[ge*4 + 1];
        float vy = edge_attr[ge*4 + 2];
        float vz = edge_attr[ge*4 + 3];
        sm[O_D + tid] = d;
        float n = sqrtf(vx*vx + vy*vy + vz*vz) + 1e-12f;
        float s = SQ3 / n;
        sm[O_Y1 + tid*4 + 0] = vx * s;
        sm[O_Y1 + tid*4 + 1] = vy * s;
        sm[O_Y1 + tid*4 + 2] = vz * s;
    }
    __syncthreads();

    // ---- pass 2: es0, rbf (into O_RBF alias), s_in node parts, v_in ----
    #pragma unroll
    for (int t = 0; t < 4; t++) {          // es0: 64x16
        int idx = tid + NT*t; int e = idx >> 4, k = idx & 15;
        float dd = sm[O_D + e] - ES_STEP * (float)k;
        sm[O_ES0 + e*17 + k] = __expf(ES_COEF * dd * dd);
    }
    #pragma unroll
    for (int t = 0; t < 32; t++) {         // rbf: 64x128 (stride 132)
        int idx = tid + NT*t; int e = idx >> 7, b = idx & 127;
        float dd = sm[O_D + e] - RBF_STEP * (float)b;
        sm[O_RBF + e*132 + b] = __expf(RBF_COEF * dd * dd);
    }
    #pragma unroll
    for (int t = 0; t < 16; t++) {         // s_in[0..63]: 64x64
        int idx = tid + NT*t; int e = idx >> 6, c = idx & 63;
        int node = (c < 32) ? smi[O_II + e] : smi[O_JJ + e];
        sm[O_SIN + e*81 + c] = node_fea[node*80 + (c & 31)] * IS80;
    }
    #pragma unroll
    for (int t = 0; t < 24; t++) {         // v_in: 64x96
        int idx = tid + NT*t; int e = idx / 96, q = idx - e*96;
        int node, f;
        if (q < 48) { node = smi[O_II + e]; f = 32 + q; }
        else        { node = smi[O_JJ + e]; f = 32 + q - 48; }
        sm[O_VIN + e*97 + q] = node_fea[node*80 + f] * IS32;
    }
    __syncthreads();

    // ---- pass 3: edge_s -> s_in[64..79], vdot ----
    #pragma unroll
    for (int t = 0; t < 4; t++) {          // edge_s: 64x16
        int idx = tid + NT*t; int e = idx >> 4, o = idx & 15;
        float a = __ldg(&b_pre[o]);
        #pragma unroll
        for (int i = 0; i < 16; i++) a += sm[O_ES0 + e*17 + i] * __ldg(&w_pre[i*16 + o]);
        sm[O_SIN + e*81 + 64 + o] = a * IS80;
    }
    #pragma unroll
    for (int t = 0; t < 8; t++) {          // vdot: 64x32
        int idx = tid + NT*t; int e = idx >> 5, i = idx & 31;
        float a = sm[O_VIN + e*97 + i*3 + 0] * sm[O_Y1 + e*4 + 0]
                + sm[O_VIN + e*97 + i*3 + 1] * sm[O_Y1 + e*4 + 1]
                + sm[O_VIN + e*97 + i*3 + 2] * sm[O_Y1 + e*4 + 2];
        sm[O_VD + e*33 + i] = a * IS3;
    }
    CP_WAIT1();            // w_rh staged (chunk0 may still fly)
    __syncthreads();

    // ---- h-GEMM: h[64e][64k] = silu(rbf[64x128] @ w_rh[128x64] + b) -> HT ----
    {
        const int eg2 = tid >> 4;   // edges 4*eg2..+3
        const int kg  = tid & 15;   // ks    4*kg ..+3
        float c[4][4];              // [kk][r]
        #pragma unroll
        for (int kk = 0; kk < 4; kk++)
            #pragma unroll
            for (int r = 0; r < 4; r++) c[kk][r] = 0.f;
        const float* rp = sm + O_RBF + eg2*4*132;
        const float* wp = sm + O_W1 + kg*4;
        #pragma unroll 2
        for (int b = 0; b < 128; b++) {
            float4 wv = *(const float4*)(wp + b*64);
            float wr[4] = {wv.x, wv.y, wv.z, wv.w};
            float rv[4];
            #pragma unroll
            for (int r = 0; r < 4; r++) rv[r] = rp[r*132 + b];
            #pragma unroll
            for (int kk = 0; kk < 4; kk++)
                #pragma unroll
                for (int r = 0; r < 4; r++) c[kk][r] += wr[kk] * rv[r];
        }
        #pragma unroll
        for (int kk = 0; kk < 4; kk++) {
            int k = 4*kg + kk;
            float bb = __ldg(&b_rh[k]);
            #pragma unroll
            for (int r = 0; r < 4; r++) {
                float z = c[kk][r] + bb;
                float h = z * sigmf(z);
                sm[O_HT + k*66 + 4*eg2 + r] = h;
            }
        }
        if (tid < 64) sm[O_HT + 64*66 + tid] = 1.0f;   // bias row of h'
    }
    __syncthreads();

    // ---- phase B: 30 chunks of 128 columns ----
    const int wid = tid >> 5, lane = tid & 31;
    const int le = tid >> 2, sub = tid & 3;
    const float yy0 = sm[O_Y1 + le*4 + 0];
    const float yy1 = sm[O_Y1 + le*4 + 1];
    const float yy2 = sm[O_Y1 + le*4 + 2];
    const float ys0 = yy0 * IS2, ys1 = yy1 * IS2, ys2 = yy2 * IS2;

    float acS[6], acV[2][3], acA[2];
    #pragma unroll
    for (int r = 0; r < 6; r++) acS[r] = 0.f;
    #pragma unroll
    for (int r = 0; r < 2; r++) { acA[r] = 0.f; acV[r][0] = acV[r][1] = acV[r][2] = 0.f; }

    for (int ch = 0; ch < 30; ch++) {
        const int base = ch << 7;
        if (ch < 29) {                      // prefetch chunk ch+1 (+ bias row)
            const int nbase = base + 128;
            const unsigned dsa = ((ch + 1) & 1) ? w1sa : w0sa;
            #pragma unroll
            for (int q = 0; q < 8; q++) {
                int fi = tid + NT*q; int k = fi >> 5, c4 = fi & 31;
                CPA16(dsa + (k*128 + c4*4)*4, w_ro + k*3840 + nbase + c4*4);
            }
            if (tid < 32) CPA16(dsa + (64*128 + tid*4)*4, b_ro + nbase + tid*4);
            CP_COMMIT();
            CP_WAIT1();
        } else {
            CP_WAIT0();
        }
        __syncthreads();

        // GEMM: warp wid computes all 64 edges x cols [wid*16, wid*16+16)
        // lane owns edges {2*lane, 2*lane+1}; w loads are warp-uniform broadcasts
        {
            const float* wb = sm + ((ch & 1) ? O_W1 : O_W0) + wid*16;
            const float* hp = sm + O_HT + 2*lane;
            unsigned long long acc[2][8];
            #pragma unroll
            for (int e = 0; e < 2; e++)
                #pragma unroll
                for (int p = 0; p < 8; p++) acc[e][p] = 0ull;
            #pragma unroll 5
            for (int k = 0; k < 65; k++) {
                float2 hv = *(const float2*)(hp + k*66);
                unsigned long long h0, h1;
                PACKDUP(h0, hv.x);
                PACKDUP(h1, hv.y);
                const float* wk = wb + k*128;
                ulonglong2 wA = *(const ulonglong2*)(wk);
                ulonglong2 wB = *(const ulonglong2*)(wk + 4);
                ulonglong2 wC = *(const ulonglong2*)(wk + 8);
                ulonglong2 wD = *(const ulonglong2*)(wk + 12);
                FMA2(acc[0][0], h0, wA.x); FMA2(acc[0][1], h0, wA.y);
                FMA2(acc[0][2], h0, wB.x); FMA2(acc[0][3], h0, wB.y);
                FMA2(acc[0][4], h0, wC.x); FMA2(acc[0][5], h0, wC.y);
                FMA2(acc[0][6], h0, wD.x); FMA2(acc[0][7], h0, wD.y);
                FMA2(acc[1][0], h1, wA.x); FMA2(acc[1][1], h1, wA.y);
                FMA2(acc[1][2], h1, wB.x); FMA2(acc[1][3], h1, wB.y);
                FMA2(acc[1][4], h1, wC.x); FMA2(acc[1][5], h1, wC.y);
                FMA2(acc[1][6], h1, wD.x); FMA2(acc[1][7], h1, wD.y);
            }
            #pragma unroll
            for (int e = 0; e < 2; e++) {
                float* dst = sm + O_WA + (2*lane + e)*132 + wid*16;
                *(ulonglong2*)(dst)      = make_ulonglong2(acc[e][0], acc[e][1]);
                *(ulonglong2*)(dst + 4)  = make_ulonglong2(acc[e][2], acc[e][3]);
                *(ulonglong2*)(dst + 8)  = make_ulonglong2(acc[e][4], acc[e][5]);
                *(ulonglong2*)(dst + 12) = make_ulonglong2(acc[e][6], acc[e][7]);
            }
        }
        __syncthreads();

        // fold chunk into register accumulators (thread owns edge le, cols c%4==sub)
        const float* wap = sm + O_WA + le*132;
        if (ch < 15) {                             // w1: s_in -> s_conv
            const float* src = sm + O_SIN + le*81 + base/24;
            switch (ch % 3) {
                case 0: foldS<0>(acS, src, wap, sub); break;
                case 1: foldS<2>(acS, src, wap, sub); break;
                default: foldS<4>(acS, src, wap, sub); break;
            }
        } else if (ch < 20) {                      // w2: s_in -> a2 (vA)
            const int i0 = (base - 1920) >> 3;
            #pragma unroll
            for (int j = 0; j < 32; j++)
                acA[j & 1] += sm[O_SIN + le*81 + i0 + (j >> 1)] * wap[4*j + sub];
        } else if (ch < 22) {                      // w3: v_in -> v_conv
            const int i0 = (base - 2560) >> 3;
            #pragma unroll
            for (int j = 0; j < 32; j++) {
                const int r = j & 1, i = i0 + (j >> 1);
                float w = wap[4*j + sub];
                acV[r][0] += sm[O_VIN + le*97 + 3*i + 0] * w;
                acV[r][1] += sm[O_VIN + le*97 + 3*i + 1] * w;
                acV[r][2] += sm[O_VIN + le*97 + 3*i + 2] * w;
            }
        } else if (ch < 28) {                      // w4: vdot -> s_conv
            const int b4 = base - 2816;
            const float* src = sm + O_VD + le*33 + b4/24;
            switch ((ch - 22) % 3) {
                case 0: foldS<0>(acS, src, wap, sub); break;
                case 1: foldS<2>(acS, src, wap, sub); break;
                default: foldS<4>(acS, src, wap, sub); break;
            }
        } else {                                   // w5: cross(v_in,Y1)/sqrt2 -> v_conv
            const int i0 = (base - 3584) >> 3;
            #pragma unroll
            for (int j = 0; j < 32; j++) {
                const int r = j & 1, i = i0 + (j >> 1);
                float w = wap[4*j + sub];
                float vx = sm[O_VIN + le*97 + 3*i + 0];
                float vy = sm[O_VIN + le*97 + 3*i + 1];
                float vz = sm[O_VIN + le*97 + 3*i + 2];
                acV[r][0] += (vy*ys2 - vz*ys1) * w;
                acV[r][1] += (vz*ys0 - vx*ys2) * w;
                acV[r][2] += (vx*ys1 - vy*ys0) * w;
            }
        }
        // next-iter top sync separates fold reads from WA writes
    }

    // ---- dump register accumulators to smem (alias over dead W buffer 0) ----
    {
        float* accd = sm + O_ACCD + le*57;
        #pragma unroll
        for (int rr = 0; rr < 6; rr++) accd[4*rr + sub] = acS[rr];
        #pragma unroll
        for (int r = 0; r < 2; r++) {
            const int o = sub + 4*r;
            accd[24 + o*3 + 0] = acV[r][0];
            accd[24 + o*3 + 1] = acV[r][1];
            accd[24 + o*3 + 2] = acV[r][2];
            accd[48 + o] = acA[r];
        }
    }
    __syncthreads();

    // ---- epilogue stage 1: silu / gating, spre+vpre into PRE rows ----
    {
        const float* accp = sm + O_ACCD + le*57;
        float g0 = sigmf(accp[16 + sub]);
        float g1 = sigmf(accp[20 + sub]);
        float aA0 = accp[48 + sub], aA1 = accp[52 + sub];
        #pragma unroll
        for (int t = 0; t < 4; t++) {
            int o = sub + 4*t;
            float z = accp[o];
            sm[O_PRE + le*41 + o] = z * sigmf(z);              // spre
        }
        float yv[3] = {yy0, yy1, yy2};
        #pragma unroll
        for (int idx = 0; idx < 2; idx++) {
            int o = sub + 4*idx;
            float aA = idx ? aA1 : aA0;
            float g  = idx ? g1  : g0;
            #pragma unroll
            for (int c = 0; c < 3; c++) {
                float v = accp[24 + o*3 + c] + aA * yv[c];     // vB+vC + vA
                sm[O_PRE + le*41 + 16 + o*3 + c] = v * g;      // vpre (gated)
            }
        }
    }
    __syncthreads();

    // ---- epilogue stage 2: post projections + sc, stats ----
    {
        const int ge = e0 + le;
        int sp = smi[O_SP + le], eb = smi[O_EB + le];
        #pragma unroll
        for (int t = 0; t < 4; t++) {
            int o = sub + 4*t;
            float a = __ldg(&b_post_s[o]);
            #pragma unroll
            for (int i = 0; i < 16; i++)
                a += sm[O_PRE + le*41 + i] * __ldg(&w_post_s[i*16 + o]);
            float sc = 0.f;
            #pragma unroll
            for (int i = 0; i < 16; i++)
                sc += sm[O_ES0 + le*17 + i] * __ldg(&w_sc[i*256 + sp*16 + o]);
            a += sc * 0.0625f;
            g_Sout[ge*16 + o] = a;
            atomicAdd(&sm[O_STAT + eb*16 + o], a);
            atomicAdd(&sm[O_STAT + 256 + eb*16 + o], a * a);
        }
        float v2 = 0.f;
        #pragma unroll
        for (int idx = 0; idx < 2; idx++) {
            int o = sub + 4*idx;
            #pragma unroll
            for (int c = 0; c < 3; c++) {
                float v = 0.f;
                #pragma unroll
                for (int i = 0; i < 8; i++)
                    v += sm[O_PRE + le*41 + 16 + i*3 + c] * __ldg(&w_post_v[i*8 + o]);
                g_Vout[ge*24 + o*3 + c] = v;
                v2 += v * v;
            }
        }
        atomicAdd(&sm[O_STAT + 512 + eb], v2);
        if (sub == 0) atomicAdd(&sm[O_STAT + 528 + eb], 1.f);
    }
    __syncthreads();
    if (tid < 256) {
        atomicAdd(&g_gs[tid],  sm[O_STAT + tid]);
        atomicAdd(&g_gs2[tid], sm[O_STAT + 256 + tid]);
    }
    if (tid < 16) {
        atomicAdd(&g_gv[tid], sm[O_STAT + 512 + tid]);
        atomicAdd(&g_gc[tid], sm[O_STAT + 528 + tid]);
    }
}

// ======================================================================
// Kernel 2: per-graph mu / inv-rms
// ======================================================================
__global__ void k_stats() {
    __shared__ float sv[256];
    int t = threadIdx.x;
    int g = t >> 4;
    float cnt = fmaxf(g_gc[g], 1.f);
    float mu = g_gs[t] / cnt;
    g_mu[t] = mu;
    sv[t] = g_gs2[t] / cnt - mu * mu;
    __syncthreads();
    if ((t & 15) == 0) {
        float a = 0.f;
        #pragma unroll
        for (int f = 0; f < 16; f++) a += sv[t + f];
        a *= (1.f / 16.f);
        g_invs[g] = 1.f / sqrtf(a + 1e-5f);
        g_invv[g] = 1.f / sqrtf(g_gv[g] / (cnt * 24.f) + 1e-5f);
    }
}

// ======================================================================
// Kernel 3: layernorm + skip + edge projections -> output
// ======================================================================
__global__ __launch_bounds__(256) void k_final(
    const float* __restrict__ edge_attr, const int* __restrict__ edge_index,
    const int*   __restrict__ batch,
    const float* __restrict__ ln_w_s, const float* __restrict__ ln_b_s,
    const float* __restrict__ ln_w_v,
    const float* __restrict__ w_skip, const float* __restrict__ w_edge_s,
    const float* __restrict__ b_edge_s, const float* __restrict__ w_edge_v,
    float* __restrict__ out)
{
    __shared__ float s_skip[256], s_es[256], s_ev[64], s_be[16];
    __shared__ float s_lws[16], s_lbs[16], s_lwv[8], s_mu[256], s_is[16], s_iv[16];
    int tid = threadIdx.x;
    s_skip[tid] = w_skip[tid];
    s_es[tid]   = w_edge_s[tid];
    s_mu[tid]   = g_mu[tid];
    if (tid < 64) s_ev[tid] = w_edge_v[tid];
    if (tid < 16) {
        s_be[tid] = b_edge_s[tid]; s_lws[tid] = ln_w_s[tid]; s_lbs[tid] = ln_b_s[tid];
        s_is[tid] = g_invs[tid];   s_iv[tid] = g_invv[tid];
    }
    if (tid < 8) s_lwv[tid] = ln_w_v[tid];
    __syncthreads();

    int ge = blockIdx.x * 256 + tid;
    int g = batch[edge_index[ge]];
    float d = edge_attr[ge*4];
    float es0[16];
    #pragma unroll
    for (int k = 0; k < 16; k++) {
        float dd = d - ES_STEP * (float)k;
        es0[k] = __expf(ES_COEF * dd * dd);
    }
    float inv_s = s_is[g], inv_v = s_iv[g];
    float sn[16];
    #pragma unroll
    for (int i = 0; i < 16; i++) {
        float sv = g_Sout[ge*16 + i];
        float v = (sv - s_mu[g*16 + i]) * inv_s * s_lws[i] + s_lbs[i];
        float sk = 0.f;
        #pragma unroll
        for (int k = 0; k < 16; k++) sk += es0[k] * s_skip[k*16 + i];
        sn[i] = v + sk;
    }
    #pragma unroll
    for (int o = 0; o < 16; o++) {
        float a = s_be[o];
        #pragma unroll
        for (int i = 0; i < 16; i++) a += sn[i] * s_es[i*16 + o];
        out[ge*40 + o] = a;
    }
    float vn[24];
    #pragma unroll
    for (int i = 0; i < 8; i++) {
        float w = inv_v * s_lwv[i];
        #pragma unroll
        for (int c = 0; c < 3; c++) vn[i*3 + c] = g_Vout[ge*24 + i*3 + c] * w;
    }
    #pragma unroll
    for (int o = 0; o < 8; o++) {
        #pragma unroll
        for (int c = 0; c < 3; c++) {
            float a = 0.f;
            #pragma unroll
            for (int i = 0; i < 8; i++) a += vn[i*3 + c] * s_ev[i*8 + o];
            out[ge*40 + 16 + o*3 + c] = a;
        }
    }
}

// ======================================================================
extern "C" void kernel_launch(void* const* d_in, const int* in_sizes, int n_in,
                              void* d_out, int out_size)
{
    const float* node_fea  = (const float*)d_in[0];
    const float* edge_attr = (const float*)d_in[1];
    const int*   edge_index= (const int*)  d_in[2];
    const int*   xs        = (const int*)  d_in[3];
    const int*   batch     = (const int*)  d_in[4];
    const float* w_rh      = (const float*)d_in[5];
    const float* b_rh      = (const float*)d_in[6];
    const float* w_ro      = (const float*)d_in[7];
    const float* b_ro      = (const float*)d_in[8];
    const float* w_pre     = (const float*)d_in[9];
    const float* b_pre     = (const float*)d_in[10];
    const float* w_sc      = (const float*)d_in[11];
    const float* w_post_s  = (const float*)d_in[12];
    const float* b_post_s  = (const float*)d_in[13];
    const float* w_post_v  = (const float*)d_in[14];
    const float* ln_w_s    = (const float*)d_in[15];
    const float* ln_b_s    = (const float*)d_in[16];
    const float* ln_w_v    = (const float*)d_in[17];
    const float* w_skip    = (const float*)d_in[18];
    const float* w_edge_s  = (const float*)d_in[19];
    const float* b_edge_s  = (const float*)d_in[20];
    const float* w_edge_v  = (const float*)d_in[21];
    float* out = (float*)d_out;

    cudaFuncSetAttribute(k_main, cudaFuncAttributeMaxDynamicSharedMemorySize, SMEM_BYTES);

    k_zero<<<1, 288>>>();
    k_main<<<EDGES/TE, NT, SMEM_BYTES>>>(
        node_fea, edge_attr, edge_index, xs, batch,
        w_rh, b_rh, w_ro, b_ro, w_pre, b_pre, w_sc,
        w_post_s, b_post_s, w_post_v);
    k_stats<<<1, 256>>>();
    k_final<<<EDGES/256, 256>>>(
        edge_attr, edge_index, batch,
        ln_w_s, ln_b_s, ln_w_v, w_skip, w_edge_s, b_edge_s, w_edge_v, out);
}

// round 14
// speedup vs baseline: 4.8086x; 1.8661x over previous
#include <cuda_runtime.h>
#include <math.h>

#define EDGES 65536
#define TE 64
#define NT 256

// ---------------- scaling constants ----------------
#define IS80 0.11180339887498949f   // 1/sqrt(80)
#define IS32 0.17677669529663687f   // 1/sqrt(32)
#define IS3  0.57735026918962576f   // 1/sqrt(3)
#define IS2  0.70710678118654752f   // 1/sqrt(2)
#define SQ3  1.73205080756887729f
#define RBF_STEP (6.0f/127.0f)
#define RBF_COEF (-0.5f/(RBF_STEP*RBF_STEP))
#define ES_STEP  0.4f
#define ES_COEF  (-3.125f)

// ---------------- global scratch ----------------
__device__ float g_Sout[EDGES*16];
__device__ float g_Vout[EDGES*24];
__device__ float g_gs[256];
__device__ float g_gs2[256];
__device__ float g_gv[16];
__device__ float g_gc[16];
__device__ float g_mu[256];
__device__ float g_invs[16];
__device__ float g_invv[16];

// ---------------- shared memory layout (float offsets) ----------------
#define O_SIN 0            // [64][81]  s_in * 1/sqrt(80)
#define O_VIN 5184         // [64][97]  v_in * 1/sqrt(32), layout i*3+c
#define O_VD  11392        // [64][33]  (v_in . Y1) / sqrt(96)
#define O_H2  13504        // [64 k][72] tf32 h: H2[k][e]
#define O_Y1  18112        // [64][4]
#define O_ES0 18368        // [64][17]
#define O_W0  19456        // [65][132] w_ro chunk buf 0 (row 64 = b_ro slice)
#define O_W1  28036        // [65][132] buf 1 (alias: w_rh staging, 8192 floats)
#define O_WA  36616        // [64][132] Wa chunk (alias: RBF [64][132] in prologue)
#define O_RBF O_WA
#define O_PRE 45064        // [64][41]  spre[16] + vpre[24]
#define O_STAT 47688       // s[256], s2[256], v[16], cnt[16]
#define O_D   48232
#define O_SP  48296
#define O_EB  48360
#define O_II  48424
#define O_JJ  48488
#define SMEM_FLOATS 48552
#define SMEM_BYTES (SMEM_FLOATS*4)
#define O_ACCD O_W0        // [64][57] epilogue acc dump (W buffers dead after loop)

__device__ __forceinline__ float sigmf(float z) { return 1.0f / (1.0f + __expf(-z)); }

__device__ __forceinline__ unsigned tf32r(float x) {
    unsigned t;
    asm("cvt.rna.tf32.f32 %0, %1;" : "=r"(t) : "f"(x));
    return t;
}

#define MMA_TF32(c, a0, a1, a2, a3, b0, b1) \
    asm volatile("mma.sync.aligned.m16n8k8.row.col.f32.tf32.tf32.f32 " \
                 "{%0,%1,%2,%3}, {%4,%5,%6,%7}, {%8,%9}, {%0,%1,%2,%3};" \
                 : "+f"((c)[0]), "+f"((c)[1]), "+f"((c)[2]), "+f"((c)[3]) \
                 : "r"(a0), "r"(a1), "r"(a2), "r"(a3), "r"(b0), "r"(b1))

#define CPA16(dst_u32, src_ptr) \
    asm volatile("cp.async.cg.shared.global [%0], [%1], 16;" :: "r"(dst_u32), "l"(src_ptr))
#define CP_COMMIT() asm volatile("cp.async.commit_group;")
#define CP_WAIT1()  asm volatile("cp.async.wait_group 1;")
#define CP_WAIT0()  asm volatile("cp.async.wait_group 0;")

// fold helper: s-type chunk (period-24 blocks), RR0 = (base%24)/4 compile-time
template<int RR0>
__device__ __forceinline__ void foldS(float acS[6], const float* __restrict__ src,
                                      const float* __restrict__ wap, int sub) {
    #pragma unroll
    for (int j = 0; j < 32; j++) {
        const int rr = (RR0 + j) % 6;
        const int di = (RR0 + j) / 6;
        acS[rr] += src[di] * wap[4*j + sub];
    }
}

// ======================================================================
// Kernel 0: zero global stats
// ======================================================================
__global__ void k_zero() {
    int t = threadIdx.x;
    if (t < 256) { g_gs[t] = 0.f; g_gs2[t] = 0.f; }
    else if (t < 272) g_gv[t-256] = 0.f;
    else if (t < 288) g_gc[t-272] = 0.f;
}

// ======================================================================
// Kernel 1: fused hypernetwork + conv + post projections + stats
// ======================================================================
__global__ __launch_bounds__(NT, 1) void k_main(
    const float* __restrict__ node_fea, const float* __restrict__ edge_attr,
    const int*   __restrict__ edge_index, const int* __restrict__ xs,
    const int*   __restrict__ batch,
    const float* __restrict__ w_rh, const float* __restrict__ b_rh,
    const float* __restrict__ w_ro, const float* __restrict__ b_ro,
    const float* __restrict__ w_pre, const float* __restrict__ b_pre,
    const float* __restrict__ w_sc,
    const float* __restrict__ w_post_s, const float* __restrict__ b_post_s,
    const float* __restrict__ w_post_v)
{
    extern __shared__ float sm[];
    int* smi = (int*)sm;
    const int tid = threadIdx.x;
    const int e0 = blockIdx.x * TE;

    const unsigned w0sa = (unsigned)__cvta_generic_to_shared(sm + O_W0);
    const unsigned w1sa = (unsigned)__cvta_generic_to_shared(sm + O_W1);

    // ---- prefetch: w_rh (group 0) then w_ro chunk 0 + bias row (group 1) ----
    #pragma unroll
    for (int q = 0; q < 8; q++) {                  // w_rh: 8192 floats contiguous
        int fi = tid + NT*q;
        CPA16(w1sa + fi*16, w_rh + fi*4);
    }
    CP_COMMIT();
    #pragma unroll
    for (int q = 0; q < 8; q++) {                  // chunk 0
        int fi = tid + NT*q; int k = fi >> 5, c4 = fi & 31;
        CPA16(w0sa + (k*132 + c4*4)*4, w_ro + k*3840 + c4*4);
    }
    if (tid < 32) CPA16(w0sa + (64*132 + tid*4)*4, b_ro + tid*4);
    CP_COMMIT();

    // ---- per-edge scalars + zero stats ----
    for (int i = tid; i < 544; i += NT) sm[O_STAT + i] = 0.f;
    if (tid < TE) {
        int ge = e0 + tid;
        int ii = edge_index[ge], jj = edge_index[EDGES + ge];
        smi[O_II + tid] = ii;
        smi[O_JJ + tid] = jj;
        smi[O_SP + tid] = 4 * xs[ii] + xs[jj];
        smi[O_EB + tid] = batch[ii];
        float d  = edge_attr[ge*4 + 0];
        float vx = edge_attr[ge*4 + 1];
        float vy = edge_attr[ge*4 + 2];
        float vz = edge_attr[ge*4 + 3];
        sm[O_D + tid] = d;
        float n = sqrtf(vx*vx + vy*vy + vz*vz) + 1e-12f;
        float s = SQ3 / n;
        sm[O_Y1 + tid*4 + 0] = vx * s;
        sm[O_Y1 + tid*4 + 1] = vy * s;
        sm[O_Y1 + tid*4 + 2] = vz * s;
    }
    __syncthreads();

    // ---- pass 2: es0, rbf (into O_RBF alias), s_in node parts, v_in ----
    #pragma unroll
    for (int t = 0; t < 4; t++) {          // es0: 64x16
        int idx = tid + NT*t; int e = idx >> 4, k = idx & 15;
        float dd = sm[O_D + e] - ES_STEP * (float)k;
        sm[O_ES0 + e*17 + k] = __expf(ES_COEF * dd * dd);
    }
    #pragma unroll
    for (int t = 0; t < 32; t++) {         // rbf: 64x128 (stride 132)
        int idx = tid + NT*t; int e = idx >> 7, b = idx & 127;
        float dd = sm[O_D + e] - RBF_STEP * (float)b;
        sm[O_RBF + e*132 + b] = __expf(RBF_COEF * dd * dd);
    }
    #pragma unroll
    for (int t = 0; t < 16; t++) {         // s_in[0..63]: 64x64
        int idx = tid + NT*t; int e = idx >> 6, c = idx & 63;
        int node = (c < 32) ? smi[O_II + e] : smi[O_JJ + e];
        sm[O_SIN + e*81 + c] = node_fea[node*80 + (c & 31)] * IS80;
    }
    #pragma unroll
    for (int t = 0; t < 24; t++) {         // v_in: 64x96
        int idx = tid + NT*t; int e = idx / 96, q = idx - e*96;
        int node, f;
        if (q < 48) { node = smi[O_II + e]; f = 32 + q; }
        else        { node = smi[O_JJ + e]; f = 32 + q - 48; }
        sm[O_VIN + e*97 + q] = node_fea[node*80 + f] * IS32;
    }
    __syncthreads();

    // ---- pass 3: edge_s -> s_in[64..79], vdot ----
    #pragma unroll
    for (int t = 0; t < 4; t++) {          // edge_s: 64x16
        int idx = tid + NT*t; int e = idx >> 4, o = idx & 15;
        float a = __ldg(&b_pre[o]);
        #pragma unroll
        for (int i = 0; i < 16; i++) a += sm[O_ES0 + e*17 + i] * __ldg(&w_pre[i*16 + o]);
        sm[O_SIN + e*81 + 64 + o] = a * IS80;
    }
    #pragma unroll
    for (int t = 0; t < 8; t++) {          // vdot: 64x32
        int idx = tid + NT*t; int e = idx >> 5, i = idx & 31;
        float a = sm[O_VIN + e*97 + i*3 + 0] * sm[O_Y1 + e*4 + 0]
                + sm[O_VIN + e*97 + i*3 + 1] * sm[O_Y1 + e*4 + 1]
                + sm[O_VIN + e*97 + i*3 + 2] * sm[O_Y1 + e*4 + 2];
        sm[O_VD + e*33 + i] = a * IS3;
    }
    CP_WAIT1();            // w_rh staged (chunk0 may still fly)
    __syncthreads();

    // ---- h-GEMM: h = silu(rbf[64x128] @ w_rh[128x64] + b) -> H2[k][e] (tf32) ----
    {
        const int eg2 = tid >> 4;   // edges 4*eg2..+3
        const int kg  = tid & 15;   // ks    4*kg ..+3
        float c[4][4];              // [kk][r]
        #pragma unroll
        for (int kk = 0; kk < 4; kk++)
            #pragma unroll
            for (int r = 0; r < 4; r++) c[kk][r] = 0.f;
        const float* rp = sm + O_RBF + eg2*4*132;
        const float* wp = sm + O_W1 + kg*4;
        #pragma unroll 2
        for (int b = 0; b < 128; b++) {
            float4 wv = *(const float4*)(wp + b*64);
            float wr[4] = {wv.x, wv.y, wv.z, wv.w};
            float rv[4];
            #pragma unroll
            for (int r = 0; r < 4; r++) rv[r] = rp[r*132 + b];
            #pragma unroll
            for (int kk = 0; kk < 4; kk++)
                #pragma unroll
                for (int r = 0; r < 4; r++) c[kk][r] += wr[kk] * rv[r];
        }
        #pragma unroll
        for (int kk = 0; kk < 4; kk++) {
            int k = 4*kg + kk;
            float bb = __ldg(&b_rh[k]);
            #pragma unroll
            for (int r = 0; r < 4; r++) {
                float z = c[kk][r] + bb;
                float h = z * sigmf(z);
                sm[O_H2 + k*72 + 4*eg2 + r] = __uint_as_float(tf32r(h));
            }
        }
    }
    __syncthreads();

    // ---- phase B: 30 chunks of 128 columns, tf32 tensor-core GEMM + fold ----
    const int wid = tid >> 5, lane = tid & 31;
    const int lg = lane >> 2, la3 = lane & 3;
    const int le = tid >> 2, sub = tid & 3;
    const float yy0 = sm[O_Y1 + le*4 + 0];
    const float yy1 = sm[O_Y1 + le*4 + 1];
    const float yy2 = sm[O_Y1 + le*4 + 2];
    const float ys0 = yy0 * IS2, ys1 = yy1 * IS2, ys2 = yy2 * IS2;

    float acS[6], acV[2][3], acA[2];
    #pragma unroll
    for (int r = 0; r < 6; r++) acS[r] = 0.f;
    #pragma unroll
    for (int r = 0; r < 2; r++) { acA[r] = 0.f; acV[r][0] = acV[r][1] = acV[r][2] = 0.f; }

    for (int ch = 0; ch < 30; ch++) {
        if (ch < 29) {                      // prefetch chunk ch+1 (+ bias row)
            const int nbase = (ch + 1) << 7;
            const unsigned dsa = ((ch + 1) & 1) ? w1sa : w0sa;
            #pragma unroll
            for (int q = 0; q < 8; q++) {
                int fi = tid + NT*q; int k = fi >> 5, c4 = fi & 31;
                CPA16(dsa + (k*132 + c4*4)*4, w_ro + k*3840 + nbase + c4*4);
            }
            if (tid < 32) CPA16(dsa + (64*132 + tid*4)*4, b_ro + nbase + tid*4);
            CP_COMMIT();
            CP_WAIT1();
        } else {
            CP_WAIT0();
        }
        __syncthreads();

        // tensor GEMM: Wa[c][e], M=cols (warp owns 16), N=edges (8 tiles), K=64
        {
            const float* wb = sm + ((ch & 1) ? O_W1 : O_W0);
            const int acol = wid*16 + lg;            // A-fragment column (m)
            float c[8][4];
            #pragma unroll
            for (int nt = 0; nt < 8; nt++)
                #pragma unroll
                for (int p = 0; p < 4; p++) c[nt][p] = 0.f;
            #pragma unroll
            for (int ks = 0; ks < 8; ks++) {
                const int k0 = ks*8 + la3;
                const float* w0 = wb + k0*132;
                const float* w4 = wb + (k0 + 4)*132;
                unsigned a0 = tf32r(w0[acol]);
                unsigned a1 = tf32r(w0[acol + 8]);
                unsigned a2 = tf32r(w4[acol]);
                unsigned a3 = tf32r(w4[acol + 8]);
                const float* h0 = sm + O_H2 + k0*72 + lg;
                const float* h4 = sm + O_H2 + (k0 + 4)*72 + lg;
                #pragma unroll
                for (int nt = 0; nt < 8; nt++) {
                    unsigned b0 = __float_as_uint(h0[nt*8]);
                    unsigned b1 = __float_as_uint(h4[nt*8]);
                    MMA_TF32(c[nt], a0, a1, a2, a3, b0, b1);
                }
            }
            // bias (staged at row 64 of chunk buffer) + writeback to WA[e][c]
            float bb0 = wb[64*132 + acol];
            float bb1 = wb[64*132 + acol + 8];
            #pragma unroll
            for (int nt = 0; nt < 8; nt++) {
                const int e = nt*8 + 2*la3;
                float* d0 = sm + O_WA + e*132 + acol;
                float* d1 = d0 + 132;
                d0[0] = c[nt][0] + bb0;
                d1[0] = c[nt][1] + bb0;
                d0[8] = c[nt][2] + bb1;
                d1[8] = c[nt][3] + bb1;
            }
        }
        __syncthreads();

        // fold chunk into register accumulators (thread owns edge le, cols c%4==sub)
        const int base = ch << 7;
        const float* wap = sm + O_WA + le*132;
        if (ch < 15) {                             // w1: s_in -> s_conv
            const float* src = sm + O_SIN + le*81 + base/24;
            switch (ch % 3) {
                case 0: foldS<0>(acS, src, wap, sub); break;
                case 1: foldS<2>(acS, src, wap, sub); break;
                default: foldS<4>(acS, src, wap, sub); break;
            }
        } else if (ch < 20) {                      // w2: s_in -> a2 (vA)
            const int i0 = (base - 1920) >> 3;
            #pragma unroll
            for (int j = 0; j < 32; j++)
                acA[j & 1] += sm[O_SIN + le*81 + i0 + (j >> 1)] * wap[4*j + sub];
        } else if (ch < 22) {                      // w3: v_in -> v_conv
            const int i0 = (base - 2560) >> 3;
            #pragma unroll
            for (int j = 0; j < 32; j++) {
                const int r = j & 1, i = i0 + (j >> 1);
                float w = wap[4*j + sub];
                acV[r][0] += sm[O_VIN + le*97 + 3*i + 0] * w;
                acV[r][1] += sm[O_VIN + le*97 + 3*i + 1] * w;
                acV[r][2] += sm[O_VIN + le*97 + 3*i + 2] * w;
            }
        } else if (ch < 28) {                      // w4: vdot -> s_conv
            const int b4 = base - 2816;
            const float* src = sm + O_VD + le*33 + b4/24;
            switch ((ch - 22) % 3) {
                case 0: foldS<0>(acS, src, wap, sub); break;
                case 1: foldS<2>(acS, src, wap, sub); break;
                default: foldS<4>(acS, src, wap, sub); break;
            }
        } else {                                   // w5: cross(v_in,Y1)/sqrt2 -> v_conv
            const int i0 = (base - 3584) >> 3;
            #pragma unroll
            for (int j = 0; j < 32; j++) {
                const int r = j & 1, i = i0 + (j >> 1);
                float w = wap[4*j + sub];
                float vx = sm[O_VIN + le*97 + 3*i + 0];
                float vy = sm[O_VIN + le*97 + 3*i + 1];
                float vz = sm[O_VIN + le*97 + 3*i + 2];
                acV[r][0] += (vy*ys2 - vz*ys1) * w;
                acV[r][1] += (vz*ys0 - vx*ys2) * w;
                acV[r][2] += (vx*ys1 - vy*ys0) * w;
            }
        }
        // next-iter top sync separates fold reads from WA writes
    }

    // ---- dump register accumulators to smem (alias over dead W buffer 0) ----
    {
        float* accd = sm + O_ACCD + le*57;
        #pragma unroll
        for (int rr = 0; rr < 6; rr++) accd[4*rr + sub] = acS[rr];
        #pragma unroll
        for (int r = 0; r < 2; r++) {
            const int o = sub + 4*r;
            accd[24 + o*3 + 0] = acV[r][0];
            accd[24 + o*3 + 1] = acV[r][1];
            accd[24 + o*3 + 2] = acV[r][2];
            accd[48 + o] = acA[r];
        }
    }
    __syncthreads();

    // ---- epilogue stage 1: silu / gating, spre+vpre into PRE rows ----
    {
        const float* accp = sm + O_ACCD + le*57;
        float g0 = sigmf(accp[16 + sub]);
        float g1 = sigmf(accp[20 + sub]);
        float aA0 = accp[48 + sub], aA1 = accp[52 + sub];
        #pragma unroll
        for (int t = 0; t < 4; t++) {
            int o = sub + 4*t;
            float z = accp[o];
            sm[O_PRE + le*41 + o] = z * sigmf(z);              // spre
        }
        float yv[3] = {yy0, yy1, yy2};
        #pragma unroll
        for (int idx = 0; idx < 2; idx++) {
            int o = sub + 4*idx;
            float aA = idx ? aA1 : aA0;
            float g  = idx ? g1  : g0;
            #pragma unroll
            for (int c = 0; c < 3; c++) {
                float v = accp[24 + o*3 + c] + aA * yv[c];     // vB+vC + vA
                sm[O_PRE + le*41 + 16 + o*3 + c] = v * g;      // vpre (gated)
            }
        }
    }
    __syncthreads();

    // ---- epilogue stage 2: post projections + sc, stats ----
    {
        const int ge = e0 + le;
        int sp = smi[O_SP + le], eb = smi[O_EB + le];
        #pragma unroll
        for (int t = 0; t < 4; t++) {
            int o = sub + 4*t;
            float a = __ldg(&b_post_s[o]);
            #pragma unroll
            for (int i = 0; i < 16; i++)
                a += sm[O_PRE + le*41 + i] * __ldg(&w_post_s[i*16 + o]);
            float sc = 0.f;
            #pragma unroll
            for (int i = 0; i < 16; i++)
                sc += sm[O_ES0 + le*17 + i] * __ldg(&w_sc[i*256 + sp*16 + o]);
            a += sc * 0.0625f;
            g_Sout[ge*16 + o] = a;
            atomicAdd(&sm[O_STAT + eb*16 + o], a);
            atomicAdd(&sm[O_STAT + 256 + eb*16 + o], a * a);
        }
        float v2 = 0.f;
        #pragma unroll
        for (int idx = 0; idx < 2; idx++) {
            int o = sub + 4*idx;
            #pragma unroll
            for (int c = 0; c < 3; c++) {
                float v = 0.f;
                #pragma unroll
                for (int i = 0; i < 8; i++)
                    v += sm[O_PRE + le*41 + 16 + i*3 + c] * __ldg(&w_post_v[i*8 + o]);
                g_Vout[ge*24 + o*3 + c] = v;
                v2 += v * v;
            }
        }
        atomicAdd(&sm[O_STAT + 512 + eb], v2);
        if (sub == 0) atomicAdd(&sm[O_STAT + 528 + eb], 1.f);
    }
    __syncthreads();
    if (tid < 256) {
        atomicAdd(&g_gs[tid],  sm[O_STAT + tid]);
        atomicAdd(&g_gs2[tid], sm[O_STAT + 256 + tid]);
    }
    if (tid < 16) {
        atomicAdd(&g_gv[tid], sm[O_STAT + 512 + tid]);
        atomicAdd(&g_gc[tid], sm[O_STAT + 528 + tid]);
    }
}

// ======================================================================
// Kernel 2: per-graph mu / inv-rms
// ======================================================================
__global__ void k_stats() {
    __shared__ float sv[256];
    int t = threadIdx.x;
    int g = t >> 4;
    float cnt = fmaxf(g_gc[g], 1.f);
    float mu = g_gs[t] / cnt;
    g_mu[t] = mu;
    sv[t] = g_gs2[t] / cnt - mu * mu;
    __syncthreads();
    if ((t & 15) == 0) {
        float a = 0.f;
        #pragma unroll
        for (int f = 0; f < 16; f++) a += sv[t + f];
        a *= (1.f / 16.f);
        g_invs[g] = 1.f / sqrtf(a + 1e-5f);
        g_invv[g] = 1.f / sqrtf(g_gv[g] / (cnt * 24.f) + 1e-5f);
    }
}

// ======================================================================
// Kernel 3: layernorm + skip + edge projections -> output
// ======================================================================
__global__ __launch_bounds__(256) void k_final(
    const float* __restrict__ edge_attr, const int* __restrict__ edge_index,
    const int*   __restrict__ batch,
    const float* __restrict__ ln_w_s, const float* __restrict__ ln_b_s,
    const float* __restrict__ ln_w_v,
    const float* __restrict__ w_skip, const float* __restrict__ w_edge_s,
    const float* __restrict__ b_edge_s, const float* __restrict__ w_edge_v,
    float* __restrict__ out)
{
    __shared__ float s_skip[256], s_es[256], s_ev[64], s_be[16];
    __shared__ float s_lws[16], s_lbs[16], s_lwv[8], s_mu[256], s_is[16], s_iv[16];
    int tid = threadIdx.x;
    s_skip[tid] = w_skip[tid];
    s_es[tid]   = w_edge_s[tid];
    s_mu[tid]   = g_mu[tid];
    if (tid < 64) s_ev[tid] = w_edge_v[tid];
    if (tid < 16) {
        s_be[tid] = b_edge_s[tid]; s_lws[tid] = ln_w_s[tid]; s_lbs[tid] = ln_b_s[tid];
        s_is[tid] = g_invs[tid];   s_iv[tid] = g_invv[tid];
    }
    if (tid < 8) s_lwv[tid] = ln_w_v[tid];
    __syncthreads();

    int ge = blockIdx.x * 256 + tid;
    int g = batch[edge_index[ge]];
    float d = edge_attr[ge*4];
    float es0[16];
    #pragma unroll
    for (int k = 0; k < 16; k++) {
        float dd = d - ES_STEP * (float)k;
        es0[k] = __expf(ES_COEF * dd * dd);
    }
    float inv_s = s_is[g], inv_v = s_iv[g];
    float sn[16];
    #pragma unroll
    for (int i = 0; i < 16; i++) {
        float sv = g_Sout[ge*16 + i];
        float v = (sv - s_mu[g*16 + i]) * inv_s * s_lws[i] + s_lbs[i];
        float sk = 0.f;
        #pragma unroll
        for (int k = 0; k < 16; k++) sk += es0[k] * s_skip[k*16 + i];
        sn[i] = v + sk;
    }
    #pragma unroll
    for (int o = 0; o < 16; o++) {
        float a = s_be[o];
        #pragma unroll
        for (int i = 0; i < 16; i++) a += sn[i] * s_es[i*16 + o];
        out[ge*40 + o] = a;
    }
    float vn[24];
    #pragma unroll
    for (int i = 0; i < 8; i++) {
        float w = inv_v * s_lwv[i];
        #pragma unroll
        for (int c = 0; c < 3; c++) vn[i*3 + c] = g_Vout[ge*24 + i*3 + c] * w;
    }
    #pragma unroll
    for (int o = 0; o < 8; o++) {
        #pragma unroll
        for (int c = 0; c < 3; c++) {
            float a = 0.f;
            #pragma unroll
            for (int i = 0; i < 8; i++) a += vn[i*3 + c] * s_ev[i*8 + o];
            out[ge*40 + 16 + o*3 + c] = a;
        }
    }
}

// ======================================================================
extern "C" void kernel_launch(void* const* d_in, const int* in_sizes, int n_in,
                              void* d_out, int out_size)
{
    const float* node_fea  = (const float*)d_in[0];
    const float* edge_attr = (const float*)d_in[1];
    const int*   edge_index= (const int*)  d_in[2];
    const int*   xs        = (const int*)  d_in[3];
    const int*   batch     = (const int*)  d_in[4];
    const float* w_rh      = (const float*)d_in[5];
    const float* b_rh      = (const float*)d_in[6];
    const float* w_ro      = (const float*)d_in[7];
    const float* b_ro      = (const float*)d_in[8];
    const float* w_pre     = (const float*)d_in[9];
    const float* b_pre     = (const float*)d_in[10];
    const float* w_sc      = (const float*)d_in[11];
    const float* w_post_s  = (const float*)d_in[12];
    const float* b_post_s  = (const float*)d_in[13];
    const float* w_post_v  = (const float*)d_in[14];
    const float* ln_w_s    = (const float*)d_in[15];
    const float* ln_b_s    = (const float*)d_in[16];
    const float* ln_w_v    = (const float*)d_in[17];
    const float* w_skip    = (const float*)d_in[18];
    const float* w_edge_s  = (const float*)d_in[19];
    const float* b_edge_s  = (const float*)d_in[20];
    const float* w_edge_v  = (const float*)d_in[21];
    float* out = (float*)d_out;

    cudaFuncSetAttribute(k_main, cudaFuncAttributeMaxDynamicSharedMemorySize, SMEM_BYTES);

    k_zero<<<1, 288>>>();
    k_main<<<EDGES/TE, NT, SMEM_BYTES>>>(
        node_fea, edge_attr, edge_index, xs, batch,
        w_rh, b_rh, w_ro, b_ro, w_pre, b_pre, w_sc,
        w_post_s, b_post_s, w_post_v);
    k_stats<<<1, 256>>>();
    k_final<<<EDGES/256, 256>>>(
        edge_attr, edge_index, batch,
        ln_w_s, ln_b_s, ln_w_v, w_skip, w_edge_s, b_edge_s, w_edge_v, out);
}

// round 15
// speedup vs baseline: 5.3803x; 1.1189x over previous
#include <cuda_runtime.h>
#include <math.h>

#define EDGES 65536
#define TE 64
#define NT 256

// ---------------- scaling constants ----------------
#define IS80 0.11180339887498949f   // 1/sqrt(80)
#define IS32 0.17677669529663687f   // 1/sqrt(32)
#define IS3  0.57735026918962576f   // 1/sqrt(3)
#define IS2  0.70710678118654752f   // 1/sqrt(2)
#define SQ3  1.73205080756887729f
#define RBF_STEP (6.0f/127.0f)
#define RBF_COEF (-0.5f/(RBF_STEP*RBF_STEP))
#define ES_STEP  0.4f
#define ES_COEF  (-3.125f)

// ---------------- global scratch ----------------
__device__ float g_Sout[EDGES*16];
__device__ float g_Vout[EDGES*24];
__device__ float g_gs[256];
__device__ float g_gs2[256];
__device__ float g_gv[16];
__device__ float g_gc[16];
__device__ float g_mu[256];
__device__ float g_invs[16];
__device__ float g_invv[16];

// ---------------- shared memory layout (float offsets) ----------------
#define O_SIN 0            // [64][81]  s_in * 1/sqrt(80)
#define O_VIN 5184         // [64][97]  v_in * 1/sqrt(32), layout i*3+c
#define O_VD  11392        // [64][33]  (v_in . Y1) / sqrt(96)
#define O_H2  13504        // [64 k][72] tf32 h: H2[k][e]
#define O_PRE O_H2         // [64][41] spre+vpre (alias; H2 dead after last GEMM)
#define O_Y1  18112        // [64][4]
#define O_ES0 18368        // [64][17]
#define O_WA  19456        // [64][132] Wa chunk (alias: RBF [64][132] in prologue)
#define O_RBF O_WA
#define O_STAT 27904       // s[256], s2[256], v[16], cnt[16]
#define O_D   28448
#define O_SP  28512
#define O_EB  28576
#define O_II  28640
#define O_JJ  28704
#define SMEM_FLOATS 28768
#define SMEM_BYTES (SMEM_FLOATS*4)

__device__ __forceinline__ float sigmf(float z) { return 1.0f / (1.0f + __expf(-z)); }

__device__ __forceinline__ unsigned tf32r(float x) {
    unsigned t;
    asm("cvt.rna.tf32.f32 %0, %1;" : "=r"(t) : "f"(x));
    return t;
}

#define MMA_TF32(c, a0, a1, a2, a3, b0, b1) \
    asm volatile("mma.sync.aligned.m16n8k8.row.col.f32.tf32.tf32.f32 " \
                 "{%0,%1,%2,%3}, {%4,%5,%6,%7}, {%8,%9}, {%0,%1,%2,%3};" \
                 : "+f"((c)[0]), "+f"((c)[1]), "+f"((c)[2]), "+f"((c)[3]) \
                 : "r"(a0), "r"(a1), "r"(a2), "r"(a3), "r"(b0), "r"(b1))

// fold helper: s-type chunk (period-24 blocks), RR0 = (base%24)/4 compile-time
template<int RR0>
__device__ __forceinline__ void foldS(float acS[6], const float* __restrict__ src,
                                      const float* __restrict__ wap, int sub) {
    #pragma unroll
    for (int j = 0; j < 32; j++) {
        const int rr = (RR0 + j) % 6;
        const int di = (RR0 + j) / 6;
        acS[rr] += src[di] * wap[4*j + sub];
    }
}

// ======================================================================
// Kernel 0: zero global stats
// ======================================================================
__global__ void k_zero() {
    int t = threadIdx.x;
    if (t < 256) { g_gs[t] = 0.f; g_gs2[t] = 0.f; }
    else if (t < 272) g_gv[t-256] = 0.f;
    else if (t < 288) g_gc[t-272] = 0.f;
}

// ======================================================================
// Kernel 1: fused hypernetwork + conv + post projections + stats
// ======================================================================
__global__ __launch_bounds__(NT, 2) void k_main(
    const float* __restrict__ node_fea, const float* __restrict__ edge_attr,
    const int*   __restrict__ edge_index, const int* __restrict__ xs,
    const int*   __restrict__ batch,
    const float* __restrict__ w_rh, const float* __restrict__ b_rh,
    const float* __restrict__ w_ro, const float* __restrict__ b_ro,
    const float* __restrict__ w_pre, const float* __restrict__ b_pre,
    const float* __restrict__ w_sc,
    const float* __restrict__ w_post_s, const float* __restrict__ b_post_s,
    const float* __restrict__ w_post_v)
{
    extern __shared__ float sm[];
    int* smi = (int*)sm;
    const int tid = threadIdx.x;
    const int e0 = blockIdx.x * TE;

    // ---- per-edge scalars + zero stats ----
    for (int i = tid; i < 544; i += NT) sm[O_STAT + i] = 0.f;
    if (tid < TE) {
        int ge = e0 + tid;
        int ii = edge_index[ge], jj = edge_index[EDGES + ge];
        smi[O_II + tid] = ii;
        smi[O_JJ + tid] = jj;
        smi[O_SP + tid] = 4 * xs[ii] + xs[jj];
        smi[O_EB + tid] = batch[ii];
        float d  = edge_attr[ge*4 + 0];
        float vx = edge_attr[ge*4 + 1];
        float vy = edge_attr[ge*4 + 2];
        float vz = edge_attr[ge*4 + 3];
        sm[O_D + tid] = d;
        float n = sqrtf(vx*vx + vy*vy + vz*vz) + 1e-12f;
        float s = SQ3 / n;
        sm[O_Y1 + tid*4 + 0] = vx * s;
        sm[O_Y1 + tid*4 + 1] = vy * s;
        sm[O_Y1 + tid*4 + 2] = vz * s;
    }
    __syncthreads();

    // ---- pass 2: es0, rbf (into O_RBF alias), s_in node parts, v_in ----
    #pragma unroll
    for (int t = 0; t < 4; t++) {          // es0: 64x16
        int idx = tid + NT*t; int e = idx >> 4, k = idx & 15;
        float dd = sm[O_D + e] - ES_STEP * (float)k;
        sm[O_ES0 + e*17 + k] = __expf(ES_COEF * dd * dd);
    }
    #pragma unroll
    for (int t = 0; t < 32; t++) {         // rbf: 64x128 (stride 132)
        int idx = tid + NT*t; int e = idx >> 7, b = idx & 127;
        float dd = sm[O_D + e] - RBF_STEP * (float)b;
        sm[O_RBF + e*132 + b] = __expf(RBF_COEF * dd * dd);
    }
    #pragma unroll
    for (int t = 0; t < 16; t++) {         // s_in[0..63]: 64x64
        int idx = tid + NT*t; int e = idx >> 6, c = idx & 63;
        int node = (c < 32) ? smi[O_II + e] : smi[O_JJ + e];
        sm[O_SIN + e*81 + c] = node_fea[node*80 + (c & 31)] * IS80;
    }
    #pragma unroll
    for (int t = 0; t < 24; t++) {         // v_in: 64x96
        int idx = tid + NT*t; int e = idx / 96, q = idx - e*96;
        int node, f;
        if (q < 48) { node = smi[O_II + e]; f = 32 + q; }
        else        { node = smi[O_JJ + e]; f = 32 + q - 48; }
        sm[O_VIN + e*97 + q] = node_fea[node*80 + f] * IS32;
    }
    __syncthreads();

    // ---- pass 3: edge_s -> s_in[64..79], vdot ----
    #pragma unroll
    for (int t = 0; t < 4; t++) {          // edge_s: 64x16
        int idx = tid + NT*t; int e = idx >> 4, o = idx & 15;
        float a = __ldg(&b_pre[o]);
        #pragma unroll
        for (int i = 0; i < 16; i++) a += sm[O_ES0 + e*17 + i] * __ldg(&w_pre[i*16 + o]);
        sm[O_SIN + e*81 + 64 + o] = a * IS80;
    }
    #pragma unroll
    for (int t = 0; t < 8; t++) {          // vdot: 64x32
        int idx = tid + NT*t; int e = idx >> 5, i = idx & 31;
        float a = sm[O_VIN + e*97 + i*3 + 0] * sm[O_Y1 + e*4 + 0]
                + sm[O_VIN + e*97 + i*3 + 1] * sm[O_Y1 + e*4 + 1]
                + sm[O_VIN + e*97 + i*3 + 2] * sm[O_Y1 + e*4 + 2];
        sm[O_VD + e*33 + i] = a * IS3;
    }
    __syncthreads();

    // ---- h-GEMM: h = silu(rbf[64x128] @ w_rh[128x64] + b) -> H2[k][e] (tf32) ----
    // w_rh read directly from global (L2-resident after first wave)
    {
        const int eg2 = tid >> 4;   // edges 4*eg2..+3
        const int kg  = tid & 15;   // ks    4*kg ..+3
        float c[4][4];              // [kk][r]
        #pragma unroll
        for (int kk = 0; kk < 4; kk++)
            #pragma unroll
            for (int r = 0; r < 4; r++) c[kk][r] = 0.f;
        const float* rp = sm + O_RBF + eg2*4*132;
        const float4* wgp = (const float4*)w_rh + kg;   // row b: b*16 + kg
        #pragma unroll 4
        for (int b = 0; b < 128; b++) {
            float4 wv = __ldg(wgp + b*16);
            float wr[4] = {wv.x, wv.y, wv.z, wv.w};
            float rv[4];
            #pragma unroll
            for (int r = 0; r < 4; r++) rv[r] = rp[r*132 + b];
            #pragma unroll
            for (int kk = 0; kk < 4; kk++)
                #pragma unroll
                for (int r = 0; r < 4; r++) c[kk][r] += wr[kk] * rv[r];
        }
        #pragma unroll
        for (int kk = 0; kk < 4; kk++) {
            int k = 4*kg + kk;
            float bb = __ldg(&b_rh[k]);
            #pragma unroll
            for (int r = 0; r < 4; r++) {
                float z = c[kk][r] + bb;
                float h = z * sigmf(z);
                sm[O_H2 + k*72 + 4*eg2 + r] = __uint_as_float(tf32r(h));
            }
        }
    }
    __syncthreads();

    // ---- phase B: 30 chunks of 128 columns, tf32 tensor-core GEMM + fold ----
    const int wid = tid >> 5, lane = tid & 31;
    const int lg = lane >> 2, la3 = lane & 3;
    const int le = tid >> 2, sub = tid & 3;
    const float yy0 = sm[O_Y1 + le*4 + 0];
    const float yy1 = sm[O_Y1 + le*4 + 1];
    const float yy2 = sm[O_Y1 + le*4 + 2];
    const float ys0 = yy0 * IS2, ys1 = yy1 * IS2, ys2 = yy2 * IS2;

    float acS[6], acV[2][3], acA[2];
    #pragma unroll
    for (int r = 0; r < 6; r++) acS[r] = 0.f;
    #pragma unroll
    for (int r = 0; r < 2; r++) { acA[r] = 0.f; acV[r][0] = acV[r][1] = acV[r][2] = 0.f; }

    const int acol = wid*16 + lg;            // A-fragment column (m)

    for (int ch = 0; ch < 30; ch++) {
        const int base = ch << 7;

        // tensor GEMM: Wa[c][e], M=cols (warp owns 16), N=edges (8 tiles), K=64
        // A fragments loaded directly from global (each element used once)
        {
            const float* wA = w_ro + base + acol;
            float af[8][4];
            #pragma unroll
            for (int ks = 0; ks < 8; ks++) {
                const int k0 = ks*8 + la3;
                af[ks][0] = __ldg(wA + k0*3840);
                af[ks][1] = __ldg(wA + k0*3840 + 8);
                af[ks][2] = __ldg(wA + (k0+4)*3840);
                af[ks][3] = __ldg(wA + (k0+4)*3840 + 8);
            }
            float c[8][4];
            #pragma unroll
            for (int nt = 0; nt < 8; nt++)
                #pragma unroll
                for (int p = 0; p < 4; p++) c[nt][p] = 0.f;
            #pragma unroll
            for (int ks = 0; ks < 8; ks++) {
                const int k0 = ks*8 + la3;
                unsigned a0 = tf32r(af[ks][0]);
                unsigned a1 = tf32r(af[ks][1]);
                unsigned a2 = tf32r(af[ks][2]);
                unsigned a3 = tf32r(af[ks][3]);
                const float* h0 = sm + O_H2 + k0*72 + lg;
                const float* h4 = h0 + 4*72;
                #pragma unroll
                for (int nt = 0; nt < 8; nt++) {
                    unsigned b0 = __float_as_uint(h0[nt*8]);
                    unsigned b1 = __float_as_uint(h4[nt*8]);
                    MMA_TF32(c[nt], a0, a1, a2, a3, b0, b1);
                }
            }
            // bias + writeback to WA[e][c]
            float bb0 = __ldg(b_ro + base + acol);
            float bb1 = __ldg(b_ro + base + acol + 8);
            #pragma unroll
            for (int nt = 0; nt < 8; nt++) {
                const int e = nt*8 + 2*la3;
                float* d0 = sm + O_WA + e*132 + acol;
                float* d1 = d0 + 132;
                d0[0] = c[nt][0] + bb0;
                d1[0] = c[nt][1] + bb0;
                d0[8] = c[nt][2] + bb1;
                d1[8] = c[nt][3] + bb1;
            }
        }
        __syncthreads();

        // fold chunk into register accumulators (thread owns edge le, cols c%4==sub)
        const float* wap = sm + O_WA + le*132;
        if (ch < 15) {                             // w1: s_in -> s_conv
            const float* src = sm + O_SIN + le*81 + base/24;
            switch (ch % 3) {
                case 0: foldS<0>(acS, src, wap, sub); break;
                case 1: foldS<2>(acS, src, wap, sub); break;
                default: foldS<4>(acS, src, wap, sub); break;
            }
        } else if (ch < 20) {                      // w2: s_in -> a2 (vA)
            const int i0 = (base - 1920) >> 3;
            #pragma unroll
            for (int j = 0; j < 32; j++)
                acA[j & 1] += sm[O_SIN + le*81 + i0 + (j >> 1)] * wap[4*j + sub];
        } else if (ch < 22) {                      // w3: v_in -> v_conv
            const int i0 = (base - 2560) >> 3;
            #pragma unroll
            for (int j = 0; j < 32; j++) {
                const int r = j & 1, i = i0 + (j >> 1);
                float w = wap[4*j + sub];
                acV[r][0] += sm[O_VIN + le*97 + 3*i + 0] * w;
                acV[r][1] += sm[O_VIN + le*97 + 3*i + 1] * w;
                acV[r][2] += sm[O_VIN + le*97 + 3*i + 2] * w;
            }
        } else if (ch < 28) {                      // w4: vdot -> s_conv
            const int b4 = base - 2816;
            const float* src = sm + O_VD + le*33 + b4/24;
            switch ((ch - 22) % 3) {
                case 0: foldS<0>(acS, src, wap, sub); break;
                case 1: foldS<2>(acS, src, wap, sub); break;
                default: foldS<4>(acS, src, wap, sub); break;
            }
        } else {                                   // w5: cross(v_in,Y1)/sqrt2 -> v_conv
            const int i0 = (base - 3584) >> 3;
            #pragma unroll
            for (int j = 0; j < 32; j++) {
                const int r = j & 1, i = i0 + (j >> 1);
                float w = wap[4*j + sub];
                float vx = sm[O_VIN + le*97 + 3*i + 0];
                float vy = sm[O_VIN + le*97 + 3*i + 1];
                float vz = sm[O_VIN + le*97 + 3*i + 2];
                acV[r][0] += (vy*ys2 - vz*ys1) * w;
                acV[r][1] += (vz*ys0 - vx*ys2) * w;
                acV[r][2] += (vx*ys1 - vy*ys0) * w;
            }
        }
        __syncthreads();   // all folds done before next chunk's WA writeback
    }

    // ---- epilogue stage 1 (thread-local): silu / gating -> PRE (aliases H2) ----
    {
        float g0 = sigmf(acS[4]);                  // s_conv[16+sub]
        float g1 = sigmf(acS[5]);                  // s_conv[20+sub]
        #pragma unroll
        for (int t = 0; t < 4; t++) {
            int o = sub + 4*t;
            float z = acS[t];
            sm[O_PRE + le*41 + o] = z * sigmf(z);          // spre
        }
        float yv[3] = {yy0, yy1, yy2};
        #pragma unroll
        for (int r = 0; r < 2; r++) {
            int o = sub + 4*r;
            float aA = acA[r];
            float g  = r ? g1 : g0;
            #pragma unroll
            for (int c = 0; c < 3; c++) {
                float v = acV[r][c] + aA * yv[c];          // vB+vC + vA
                sm[O_PRE + le*41 + 16 + o*3 + c] = v * g;  // vpre (gated)
            }
        }
    }
    __syncthreads();

    // ---- epilogue stage 2: post projections + sc, stats ----
    {
        const int ge = e0 + le;
        int sp = smi[O_SP + le], eb = smi[O_EB + le];
        #pragma unroll
        for (int t = 0; t < 4; t++) {
            int o = sub + 4*t;
            float a = __ldg(&b_post_s[o]);
            #pragma unroll
            for (int i = 0; i < 16; i++)
                a += sm[O_PRE + le*41 + i] * __ldg(&w_post_s[i*16 + o]);
            float sc = 0.f;
            #pragma unroll
            for (int i = 0; i < 16; i++)
                sc += sm[O_ES0 + le*17 + i] * __ldg(&w_sc[i*256 + sp*16 + o]);
            a += sc * 0.0625f;
            g_Sout[ge*16 + o] = a;
            atomicAdd(&sm[O_STAT + eb*16 + o], a);
            atomicAdd(&sm[O_STAT + 256 + eb*16 + o], a * a);
        }
        float v2 = 0.f;
        #pragma unroll
        for (int idx = 0; idx < 2; idx++) {
            int o = sub + 4*idx;
            #pragma unroll
            for (int c = 0; c < 3; c++) {
                float v = 0.f;
                #pragma unroll
                for (int i = 0; i < 8; i++)
                    v += sm[O_PRE + le*41 + 16 + i*3 + c] * __ldg(&w_post_v[i*8 + o]);
                g_Vout[ge*24 + o*3 + c] = v;
                v2 += v * v;
            }
        }
        atomicAdd(&sm[O_STAT + 512 + eb], v2);
        if (sub == 0) atomicAdd(&sm[O_STAT + 528 + eb], 1.f);
    }
    __syncthreads();
    if (tid < 256) {
        atomicAdd(&g_gs[tid],  sm[O_STAT + tid]);
        atomicAdd(&g_gs2[tid], sm[O_STAT + 256 + tid]);
    }
    if (tid < 16) {
        atomicAdd(&g_gv[tid], sm[O_STAT + 512 + tid]);
        atomicAdd(&g_gc[tid], sm[O_STAT + 528 + tid]);
    }
}

// ======================================================================
// Kernel 2: per-graph mu / inv-rms
// ======================================================================
__global__ void k_stats() {
    __shared__ float sv[256];
    int t = threadIdx.x;
    int g = t >> 4;
    float cnt = fmaxf(g_gc[g], 1.f);
    float mu = g_gs[t] / cnt;
    g_mu[t] = mu;
    sv[t] = g_gs2[t] / cnt - mu * mu;
    __syncthreads();
    if ((t & 15) == 0) {
        float a = 0.f;
        #pragma unroll
        for (int f = 0; f < 16; f++) a += sv[t + f];
        a *= (1.f / 16.f);
        g_invs[g] = 1.f / sqrtf(a + 1e-5f);
        g_invv[g] = 1.f / sqrtf(g_gv[g] / (cnt * 24.f) + 1e-5f);
    }
}

// ======================================================================
// Kernel 3: layernorm + skip + edge projections -> output
// ======================================================================
__global__ __launch_bounds__(256) void k_final(
    const float* __restrict__ edge_attr, const int* __restrict__ edge_index,
    const int*   __restrict__ batch,
    const float* __restrict__ ln_w_s, const float* __restrict__ ln_b_s,
    const float* __restrict__ ln_w_v,
    const float* __restrict__ w_skip, const float* __restrict__ w_edge_s,
    const float* __restrict__ b_edge_s, const float* __restrict__ w_edge_v,
    float* __restrict__ out)
{
    __shared__ float s_skip[256], s_es[256], s_ev[64], s_be[16];
    __shared__ float s_lws[16], s_lbs[16], s_lwv[8], s_mu[256], s_is[16], s_iv[16];
    int tid = threadIdx.x;
    s_skip[tid] = w_skip[tid];
    s_es[tid]   = w_edge_s[tid];
    s_mu[tid]   = g_mu[tid];
    if (tid < 64) s_ev[tid] = w_edge_v[tid];
    if (tid < 16) {
        s_be[tid] = b_edge_s[tid]; s_lws[tid] = ln_w_s[tid]; s_lbs[tid] = ln_b_s[tid];
        s_is[tid] = g_invs[tid];   s_iv[tid] = g_invv[tid];
    }
    if (tid < 8) s_lwv[tid] = ln_w_v[tid];
    __syncthreads();

    int ge = blockIdx.x * 256 + tid;
    int g = batch[edge_index[ge]];
    float d = edge_attr[ge*4];
    float es0[16];
    #pragma unroll
    for (int k = 0; k < 16; k++) {
        float dd = d - ES_STEP * (float)k;
        es0[k] = __expf(ES_COEF * dd * dd);
    }
    float inv_s = s_is[g], inv_v = s_iv[g];
    float sn[16];
    #pragma unroll
    for (int i = 0; i < 16; i++) {
        float sv = g_Sout[ge*16 + i];
        float v = (sv - s_mu[g*16 + i]) * inv_s * s_lws[i] + s_lbs[i];
        float sk = 0.f;
        #pragma unroll
        for (int k = 0; k < 16; k++) sk += es0[k] * s_skip[k*16 + i];
        sn[i] = v + sk;
    }
    #pragma unroll
    for (int o = 0; o < 16; o++) {
        float a = s_be[o];
        #pragma unroll
        for (int i = 0; i < 16; i++) a += sn[i] * s_es[i*16 + o];
        out[ge*40 + o] = a;
    }
    float vn[24];
    #pragma unroll
    for (int i = 0; i < 8; i++) {
        float w = inv_v * s_lwv[i];
        #pragma unroll
        for (int c = 0; c < 3; c++) vn[i*3 + c] = g_Vout[ge*24 + i*3 + c] * w;
    }
    #pragma unroll
    for (int o = 0; o < 8; o++) {
        #pragma unroll
        for (int c = 0; c < 3; c++) {
            float a = 0.f;
            #pragma unroll
            for (int i = 0; i < 8; i++) a += vn[i*3 + c] * s_ev[i*8 + o];
            out[ge*40 + 16 + o*3 + c] = a;
        }
    }
}

// ======================================================================
extern "C" void kernel_launch(void* const* d_in, const int* in_sizes, int n_in,
                              void* d_out, int out_size)
{
    const float* node_fea  = (const float*)d_in[0];
    const float* edge_attr = (const float*)d_in[1];
    const int*   edge_index= (const int*)  d_in[2];
    const int*   xs        = (const int*)  d_in[3];
    const int*   batch     = (const int*)  d_in[4];
    const float* w_rh      = (const float*)d_in[5];
    const float* b_rh      = (const float*)d_in[6];
    const float* w_ro      = (const float*)d_in[7];
    const float* b_ro      = (const float*)d_in[8];
    const float* w_pre     = (const float*)d_in[9];
    const float* b_pre     = (const float*)d_in[10];
    const float* w_sc      = (const float*)d_in[11];
    const float* w_post_s  = (const float*)d_in[12];
    const float* b_post_s  = (const float*)d_in[13];
    const float* w_post_v  = (const float*)d_in[14];
    const float* ln_w_s    = (const float*)d_in[15];
    const float* ln_b_s    = (const float*)d_in[16];
    const float* ln_w_v    = (const float*)d_in[17];
    const float* w_skip    = (const float*)d_in[18];
    const float* w_edge_s  = (const float*)d_in[19];
    const float* b_edge_s  = (const float*)d_in[20];
    const float* w_edge_v  = (const float*)d_in[21];
    float* out = (float*)d_out;

    cudaFuncSetAttribute(k_main, cudaFuncAttributeMaxDynamicSharedMemorySize, SMEM_BYTES);

    k_zero<<<1, 288>>>();
    k_main<<<EDGES/TE, NT, SMEM_BYTES>>>(
        node_fea, edge_attr, edge_index, xs, batch,
        w_rh, b_rh, w_ro, b_ro, w_pre, b_pre, w_sc,
        w_post_s, b_post_s, w_post_v);
    k_stats<<<1, 256>>>();
    k_final<<<EDGES/256, 256>>>(
        edge_attr, edge_index, batch,
        ln_w_s, ln_b_s, ln_w_v, w_skip, w_edge_s, b_edge_s, w_edge_v, out);
}

// round 16
// speedup vs baseline: 6.4838x; 1.2051x over previous
#include <cuda_runtime.h>
#include <math.h>

#define EDGES 65536
#define TE 64
#define NT 256

// ---------------- scaling constants ----------------
#define IS80 0.11180339887498949f   // 1/sqrt(80)
#define IS32 0.17677669529663687f   // 1/sqrt(32)
#define IS3  0.57735026918962576f   // 1/sqrt(3)
#define IS2  0.70710678118654752f   // 1/sqrt(2)
#define SQ3  1.73205080756887729f
#define RBF_STEP (6.0f/127.0f)
#define RBF_COEF (-0.5f/(RBF_STEP*RBF_STEP))
#define ES_STEP  0.4f
#define ES_COEF  (-3.125f)

// ---------------- global scratch ----------------
__device__ float g_Sout[EDGES*16];
__device__ float g_Vout[EDGES*24];
__device__ float4 g_Wp4[61440];     // w_ro permuted to A-fragment order (tf32 bits)
__device__ float g_gs[256];
__device__ float g_gs2[256];
__device__ float g_gv[16];
__device__ float g_gc[16];
__device__ float g_mu[256];
__device__ float g_invs[16];
__device__ float g_invv[16];

// ---------------- shared memory layout (float offsets) ----------------
#define O_SIN 0            // [64][81]  s_in * 1/sqrt(80)
#define O_VIN 5184         // [64][97]  v_in * 1/sqrt(32), layout i*3+c
#define O_VD  11392        // [64][33]  (v_in . Y1) / sqrt(96)
#define O_H2  13504        // [64 k][72] tf32 h: H2[k][e]
#define O_PRE O_H2         // [64][41] spre+vpre (alias; H2 dead after last GEMM)
#define O_Y1  18112        // [64][4]
#define O_ES0 18368        // [64][17]
#define O_WA  19456        // [64][132] Wa chunk (alias: RBF [64][132] in prologue)
#define O_RBF O_WA
#define O_STAT 27904       // s[256], s2[256], v[16], cnt[16]
#define O_D   28448
#define O_SP  28512
#define O_EB  28576
#define O_II  28640
#define O_JJ  28704
#define SMEM_FLOATS 28768
#define SMEM_BYTES (SMEM_FLOATS*4)

__device__ __forceinline__ float sigmf(float z) { return 1.0f / (1.0f + __expf(-z)); }

__device__ __forceinline__ unsigned tf32r(float x) {
    unsigned t;
    asm("cvt.rna.tf32.f32 %0, %1;" : "=r"(t) : "f"(x));
    return t;
}

#define MMA_TF32(c, a0, a1, a2, a3, b0, b1) \
    asm volatile("mma.sync.aligned.m16n8k8.row.col.f32.tf32.tf32.f32 " \
                 "{%0,%1,%2,%3}, {%4,%5,%6,%7}, {%8,%9}, {%0,%1,%2,%3};" \
                 : "+f"((c)[0]), "+f"((c)[1]), "+f"((c)[2]), "+f"((c)[3]) \
                 : "r"(a0), "r"(a1), "r"(a2), "r"(a3), "r"(b0), "r"(b1))

// fold helper: s-type chunk (period-24 blocks), RR0 = (base%24)/4 compile-time
template<int RR0>
__device__ __forceinline__ void foldS(float acS[6], const float* __restrict__ src,
                                      const float* __restrict__ wap, int sub) {
    #pragma unroll
    for (int j = 0; j < 32; j++) {
        const int rr = (RR0 + j) % 6;
        const int di = (RR0 + j) / 6;
        acS[rr] += src[di] * wap[4*j + sub];
    }
}

// ======================================================================
// Kernel 0: zero global stats
// ======================================================================
__global__ void k_zero() {
    int t = threadIdx.x;
    if (t < 256) { g_gs[t] = 0.f; g_gs2[t] = 0.f; }
    else if (t < 272) g_gv[t-256] = 0.f;
    else if (t < 288) g_gc[t-272] = 0.f;
}

// ======================================================================
// Kernel P: permute w_ro into per-thread A-fragment order (tf32-rounded)
//   idx4 = ((ch*8 + wid)*8 + ks)*32 + lane ; payload {a0,a1,a2,a3}
// ======================================================================
__global__ __launch_bounds__(256) void k_prep(const float* __restrict__ w_ro) {
    int idx4 = blockIdx.x * 256 + threadIdx.x;      // 0..61439
    int lane = idx4 & 31;
    int ks   = (idx4 >> 5) & 7;
    int wid  = (idx4 >> 8) & 7;
    int ch   = idx4 >> 11;
    int lg = lane >> 2, la3 = lane & 3;
    int acol = wid*16 + lg;
    int k0 = ks*8 + la3;
    const float* p = w_ro + ch*128 + acol;
    float4 v;
    v.x = __uint_as_float(tf32r(__ldg(p + k0*3840)));
    v.y = __uint_as_float(tf32r(__ldg(p + k0*3840 + 8)));
    v.z = __uint_as_float(tf32r(__ldg(p + (k0+4)*3840)));
    v.w = __uint_as_float(tf32r(__ldg(p + (k0+4)*3840 + 8)));
    g_Wp4[idx4] = v;
}

// ======================================================================
// Kernel 1: fused hypernetwork + conv + post projections + stats
// ======================================================================
__global__ __launch_bounds__(NT, 2) void k_main(
    const float* __restrict__ node_fea, const float* __restrict__ edge_attr,
    const int*   __restrict__ edge_index, const int* __restrict__ xs,
    const int*   __restrict__ batch,
    const float* __restrict__ w_rh, const float* __restrict__ b_rh,
    const float* __restrict__ w_ro, const float* __restrict__ b_ro,
    const float* __restrict__ w_pre, const float* __restrict__ b_pre,
    const float* __restrict__ w_sc,
    const float* __restrict__ w_post_s, const float* __restrict__ b_post_s,
    const float* __restrict__ w_post_v)
{
    extern __shared__ float sm[];
    int* smi = (int*)sm;
    const int tid = threadIdx.x;
    const int e0 = blockIdx.x * TE;

    // ---- per-edge scalars + zero stats ----
    for (int i = tid; i < 544; i += NT) sm[O_STAT + i] = 0.f;
    if (tid < TE) {
        int ge = e0 + tid;
        int ii = edge_index[ge], jj = edge_index[EDGES + ge];
        smi[O_II + tid] = ii;
        smi[O_JJ + tid] = jj;
        smi[O_SP + tid] = 4 * xs[ii] + xs[jj];
        smi[O_EB + tid] = batch[ii];
        float d  = edge_attr[ge*4 + 0];
        float vx = edge_attr[ge*4 + 1];
        float vy = edge_attr[ge*4 + 2];
        float vz = edge_attr[ge*4 + 3];
        sm[O_D + tid] = d;
        float n = sqrtf(vx*vx + vy*vy + vz*vz) + 1e-12f;
        float s = SQ3 / n;
        sm[O_Y1 + tid*4 + 0] = vx * s;
        sm[O_Y1 + tid*4 + 1] = vy * s;
        sm[O_Y1 + tid*4 + 2] = vz * s;
    }
    __syncthreads();

    // ---- pass 2: es0, rbf (into O_RBF alias), s_in node parts, v_in ----
    #pragma unroll
    for (int t = 0; t < 4; t++) {          // es0: 64x16
        int idx = tid + NT*t; int e = idx >> 4, k = idx & 15;
        float dd = sm[O_D + e] - ES_STEP * (float)k;
        sm[O_ES0 + e*17 + k] = __expf(ES_COEF * dd * dd);
    }
    #pragma unroll
    for (int t = 0; t < 32; t++) {         // rbf: 64x128 (stride 132)
        int idx = tid + NT*t; int e = idx >> 7, b = idx & 127;
        float dd = sm[O_D + e] - RBF_STEP * (float)b;
        sm[O_RBF + e*132 + b] = __expf(RBF_COEF * dd * dd);
    }
    #pragma unroll
    for (int t = 0; t < 16; t++) {         // s_in[0..63]: 64x64
        int idx = tid + NT*t; int e = idx >> 6, c = idx & 63;
        int node = (c < 32) ? smi[O_II + e] : smi[O_JJ + e];
        sm[O_SIN + e*81 + c] = node_fea[node*80 + (c & 31)] * IS80;
    }
    #pragma unroll
    for (int t = 0; t < 24; t++) {         // v_in: 64x96
        int idx = tid + NT*t; int e = idx / 96, q = idx - e*96;
        int node, f;
        if (q < 48) { node = smi[O_II + e]; f = 32 + q; }
        else        { node = smi[O_JJ + e]; f = 32 + q - 48; }
        sm[O_VIN + e*97 + q] = node_fea[node*80 + f] * IS32;
    }
    __syncthreads();

    // ---- pass 3: edge_s -> s_in[64..79], vdot ----
    #pragma unroll
    for (int t = 0; t < 4; t++) {          // edge_s: 64x16
        int idx = tid + NT*t; int e = idx >> 4, o = idx & 15;
        float a = __ldg(&b_pre[o]);
        #pragma unroll
        for (int i = 0; i < 16; i++) a += sm[O_ES0 + e*17 + i] * __ldg(&w_pre[i*16 + o]);
        sm[O_SIN + e*81 + 64 + o] = a * IS80;
    }
    #pragma unroll
    for (int t = 0; t < 8; t++) {          // vdot: 64x32
        int idx = tid + NT*t; int e = idx >> 5, i = idx & 31;
        float a = sm[O_VIN + e*97 + i*3 + 0] * sm[O_Y1 + e*4 + 0]
                + sm[O_VIN + e*97 + i*3 + 1] * sm[O_Y1 + e*4 + 1]
                + sm[O_VIN + e*97 + i*3 + 2] * sm[O_Y1 + e*4 + 2];
        sm[O_VD + e*33 + i] = a * IS3;
    }
    __syncthreads();

    // ---- h-GEMM: h = silu(rbf[64x128] @ w_rh[128x64] + b) -> H2[k][e] (tf32) ----
    // w_rh read directly from global (L1/L2-resident)
    {
        const int eg2 = tid >> 4;   // edges 4*eg2..+3
        const int kg  = tid & 15;   // ks    4*kg ..+3
        float c[4][4];              // [kk][r]
        #pragma unroll
        for (int kk = 0; kk < 4; kk++)
            #pragma unroll
            for (int r = 0; r < 4; r++) c[kk][r] = 0.f;
        const float* rp = sm + O_RBF + eg2*4*132;
        const float4* wgp = (const float4*)w_rh + kg;   // row b: b*16 + kg
        #pragma unroll 4
        for (int b = 0; b < 128; b++) {
            float4 wv = __ldg(wgp + b*16);
            float wr[4] = {wv.x, wv.y, wv.z, wv.w};
            float rv[4];
            #pragma unroll
            for (int r = 0; r < 4; r++) rv[r] = rp[r*132 + b];
            #pragma unroll
            for (int kk = 0; kk < 4; kk++)
                #pragma unroll
                for (int r = 0; r < 4; r++) c[kk][r] += wr[kk] * rv[r];
        }
        #pragma unroll
        for (int kk = 0; kk < 4; kk++) {
            int k = 4*kg + kk;
            float bb = __ldg(&b_rh[k]);
            #pragma unroll
            for (int r = 0; r < 4; r++) {
                float z = c[kk][r] + bb;
                float h = z * sigmf(z);
                sm[O_H2 + k*72 + 4*eg2 + r] = __uint_as_float(tf32r(h));
            }
        }
    }
    __syncthreads();

    // ---- phase B: 30 chunks of 128 columns, tf32 tensor-core GEMM + fold ----
    const int wid = tid >> 5, lane = tid & 31;
    const int lg = lane >> 2, la3 = lane & 3;
    const int le = tid >> 2, sub = tid & 3;
    const float yy0 = sm[O_Y1 + le*4 + 0];
    const float yy1 = sm[O_Y1 + le*4 + 1];
    const float yy2 = sm[O_Y1 + le*4 + 2];
    const float ys0 = yy0 * IS2, ys1 = yy1 * IS2, ys2 = yy2 * IS2;

    float acS[6], acV[2][3], acA[2];
    #pragma unroll
    for (int r = 0; r < 6; r++) acS[r] = 0.f;
    #pragma unroll
    for (int r = 0; r < 2; r++) { acA[r] = 0.f; acV[r][0] = acV[r][1] = acV[r][2] = 0.f; }

    const int acol = wid*16 + lg;            // A-fragment column (m)
    const float4* wpw = g_Wp4 + wid*256 + lane;   // + ch*2048 + ks*32

    for (int ch = 0; ch < 30; ch++) {
        const int base = ch << 7;

        // tensor GEMM: Wa[c][e], M=cols (warp owns 16), N=edges (8 tiles), K=64
        // A fragments: pre-permuted, tf32-rounded, coalesced LDG.128
        {
            const float4* wp = wpw + ch*2048;
            float4 af[8];
            #pragma unroll
            for (int ks = 0; ks < 8; ks++) af[ks] = __ldg(wp + ks*32);
            float c[8][4];
            #pragma unroll
            for (int nt = 0; nt < 8; nt++)
                #pragma unroll
                for (int p = 0; p < 4; p++) c[nt][p] = 0.f;
            #pragma unroll
            for (int ks = 0; ks < 8; ks++) {
                const int k0 = ks*8 + la3;
                unsigned a0 = __float_as_uint(af[ks].x);
                unsigned a1 = __float_as_uint(af[ks].y);
                unsigned a2 = __float_as_uint(af[ks].z);
                unsigned a3 = __float_as_uint(af[ks].w);
                const float* h0 = sm + O_H2 + k0*72 + lg;
                const float* h4 = h0 + 4*72;
                #pragma unroll
                for (int nt = 0; nt < 8; nt++) {
                    unsigned b0 = __float_as_uint(h0[nt*8]);
                    unsigned b1 = __float_as_uint(h4[nt*8]);
                    MMA_TF32(c[nt], a0, a1, a2, a3, b0, b1);
                }
            }
            // bias + writeback to WA[e][c]
            float bb0 = __ldg(b_ro + base + acol);
            float bb1 = __ldg(b_ro + base + acol + 8);
            #pragma unroll
            for (int nt = 0; nt < 8; nt++) {
                const int e = nt*8 + 2*la3;
                float* d0 = sm + O_WA + e*132 + acol;
                float* d1 = d0 + 132;
                d0[0] = c[nt][0] + bb0;
                d1[0] = c[nt][1] + bb0;
                d0[8] = c[nt][2] + bb1;
                d1[8] = c[nt][3] + bb1;
            }
        }
        __syncthreads();

        // fold chunk into register accumulators (thread owns edge le, cols c%4==sub)
        const float* wap = sm + O_WA + le*132;
        if (ch < 15) {                             // w1: s_in -> s_conv
            const float* src = sm + O_SIN + le*81 + base/24;
            switch (ch % 3) {
                case 0: foldS<0>(acS, src, wap, sub); break;
                case 1: foldS<2>(acS, src, wap, sub); break;
                default: foldS<4>(acS, src, wap, sub); break;
            }
        } else if (ch < 20) {                      // w2: s_in -> a2 (vA)
            const int i0 = (base - 1920) >> 3;
            #pragma unroll
            for (int j = 0; j < 32; j++)
                acA[j & 1] += sm[O_SIN + le*81 + i0 + (j >> 1)] * wap[4*j + sub];
        } else if (ch < 22) {                      // w3: v_in -> v_conv
            const int i0 = (base - 2560) >> 3;
            #pragma unroll
            for (int j = 0; j < 32; j++) {
                const int r = j & 1, i = i0 + (j >> 1);
                float w = wap[4*j + sub];
                acV[r][0] += sm[O_VIN + le*97 + 3*i + 0] * w;
                acV[r][1] += sm[O_VIN + le*97 + 3*i + 1] * w;
                acV[r][2] += sm[O_VIN + le*97 + 3*i + 2] * w;
            }
        } else if (ch < 28) {                      // w4: vdot -> s_conv
            const int b4 = base - 2816;
            const float* src = sm + O_VD + le*33 + b4/24;
            switch ((ch - 22) % 3) {
                case 0: foldS<0>(acS, src, wap, sub); break;
                case 1: foldS<2>(acS, src, wap, sub); break;
                default: foldS<4>(acS, src, wap, sub); break;
            }
        } else {                                   // w5: cross(v_in,Y1)/sqrt2 -> v_conv
            const int i0 = (base - 3584) >> 3;
            #pragma unroll
            for (int j = 0; j < 32; j++) {
                const int r = j & 1, i = i0 + (j >> 1);
                float w = wap[4*j + sub];
                float vx = sm[O_VIN + le*97 + 3*i + 0];
                float vy = sm[O_VIN + le*97 + 3*i + 1];
                float vz = sm[O_VIN + le*97 + 3*i + 2];
                acV[r][0] += (vy*ys2 - vz*ys1) * w;
                acV[r][1] += (vz*ys0 - vx*ys2) * w;
                acV[r][2] += (vx*ys1 - vy*ys0) * w;
            }
        }
        __syncthreads();   // all folds done before next chunk's WA writeback
    }

    // ---- epilogue stage 1 (thread-local): silu / gating -> PRE (aliases H2) ----
    {
        float g0 = sigmf(acS[4]);                  // s_conv[16+sub]
        float g1 = sigmf(acS[5]);                  // s_conv[20+sub]
        #pragma unroll
        for (int t = 0; t < 4; t++) {
            int o = sub + 4*t;
            float z = acS[t];
            sm[O_PRE + le*41 + o] = z * sigmf(z);          // spre
        }
        float yv[3] = {yy0, yy1, yy2};
        #pragma unroll
        for (int r = 0; r < 2; r++) {
            int o = sub + 4*r;
            float aA = acA[r];
            float g  = r ? g1 : g0;
            #pragma unroll
            for (int c = 0; c < 3; c++) {
                float v = acV[r][c] + aA * yv[c];          // vB+vC + vA
                sm[O_PRE + le*41 + 16 + o*3 + c] = v * g;  // vpre (gated)
            }
        }
    }
    __syncthreads();

    // ---- epilogue stage 2: post projections + sc, stats ----
    {
        const int ge = e0 + le;
        int sp = smi[O_SP + le], eb = smi[O_EB + le];
        #pragma unroll
        for (int t = 0; t < 4; t++) {
            int o = sub + 4*t;
            float a = __ldg(&b_post_s[o]);
            #pragma unroll
            for (int i = 0; i < 16; i++)
                a += sm[O_PRE + le*41 + i] * __ldg(&w_post_s[i*16 + o]);
            float sc = 0.f;
            #pragma unroll
            for (int i = 0; i < 16; i++)
                sc += sm[O_ES0 + le*17 + i] * __ldg(&w_sc[i*256 + sp*16 + o]);
            a += sc * 0.0625f;
            g_Sout[ge*16 + o] = a;
            atomicAdd(&sm[O_STAT + eb*16 + o], a);
            atomicAdd(&sm[O_STAT + 256 + eb*16 + o], a * a);
        }
        float v2 = 0.f;
        #pragma unroll
        for (int idx = 0; idx < 2; idx++) {
            int o = sub + 4*idx;
            #pragma unroll
            for (int c = 0; c < 3; c++) {
                float v = 0.f;
                #pragma unroll
                for (int i = 0; i < 8; i++)
                    v += sm[O_PRE + le*41 + 16 + i*3 + c] * __ldg(&w_post_v[i*8 + o]);
                g_Vout[ge*24 + o*3 + c] = v;
                v2 += v * v;
            }
        }
        atomicAdd(&sm[O_STAT + 512 + eb], v2);
        if (sub == 0) atomicAdd(&sm[O_STAT + 528 + eb], 1.f);
    }
    __syncthreads();
    if (tid < 256) {
        atomicAdd(&g_gs[tid],  sm[O_STAT + tid]);
        atomicAdd(&g_gs2[tid], sm[O_STAT + 256 + tid]);
    }
    if (tid < 16) {
        atomicAdd(&g_gv[tid], sm[O_STAT + 512 + tid]);
        atomicAdd(&g_gc[tid], sm[O_STAT + 528 + tid]);
    }
}

// ======================================================================
// Kernel 2: per-graph mu / inv-rms
// ======================================================================
__global__ void k_stats() {
    __shared__ float sv[256];
    int t = threadIdx.x;
    int g = t >> 4;
    float cnt = fmaxf(g_gc[g], 1.f);
    float mu = g_gs[t] / cnt;
    g_mu[t] = mu;
    sv[t] = g_gs2[t] / cnt - mu * mu;
    __syncthreads();
    if ((t & 15) == 0) {
        float a = 0.f;
        #pragma unroll
        for (int f = 0; f < 16; f++) a += sv[t + f];
        a *= (1.f / 16.f);
        g_invs[g] = 1.f / sqrtf(a + 1e-5f);
        g_invv[g] = 1.f / sqrtf(g_gv[g] / (cnt * 24.f) + 1e-5f);
    }
}

// ======================================================================
// Kernel 3: layernorm + skip + edge projections -> output
// ======================================================================
__global__ __launch_bounds__(256) void k_final(
    const float* __restrict__ edge_attr, const int* __restrict__ edge_index,
    const int*   __restrict__ batch,
    const float* __restrict__ ln_w_s, const float* __restrict__ ln_b_s,
    const float* __restrict__ ln_w_v,
    const float* __restrict__ w_skip, const float* __restrict__ w_edge_s,
    const float* __restrict__ b_edge_s, const float* __restrict__ w_edge_v,
    float* __restrict__ out)
{
    __shared__ float s_skip[256], s_es[256], s_ev[64], s_be[16];
    __shared__ float s_lws[16], s_lbs[16], s_lwv[8], s_mu[256], s_is[16], s_iv[16];
    int tid = threadIdx.x;
    s_skip[tid] = w_skip[tid];
    s_es[tid]   = w_edge_s[tid];
    s_mu[tid]   = g_mu[tid];
    if (tid < 64) s_ev[tid] = w_edge_v[tid];
    if (tid < 16) {
        s_be[tid] = b_edge_s[tid]; s_lws[tid] = ln_w_s[tid]; s_lbs[tid] = ln_b_s[tid];
        s_is[tid] = g_invs[tid];   s_iv[tid] = g_invv[tid];
    }
    if (tid < 8) s_lwv[tid] = ln_w_v[tid];
    __syncthreads();

    int ge = blockIdx.x * 256 + tid;
    int g = batch[edge_index[ge]];
    float d = edge_attr[ge*4];
    float es0[16];
    #pragma unroll
    for (int k = 0; k < 16; k++) {
        float dd = d - ES_STEP * (float)k;
        es0[k] = __expf(ES_COEF * dd * dd);
    }
    float inv_s = s_is[g], inv_v = s_iv[g];
    float sn[16];
    #pragma unroll
    for (int i = 0; i < 16; i++) {
        float sv = g_Sout[ge*16 + i];
        float v = (sv - s_mu[g*16 + i]) * inv_s * s_lws[i] + s_lbs[i];
        float sk = 0.f;
        #pragma unroll
        for (int k = 0; k < 16; k++) sk += es0[k] * s_skip[k*16 + i];
        sn[i] = v + sk;
    }
    #pragma unroll
    for (int o = 0; o < 16; o++) {
        float a = s_be[o];
        #pragma unroll
        for (int i = 0; i < 16; i++) a += sn[i] * s_es[i*16 + o];
        out[ge*40 + o] = a;
    }
    float vn[24];
    #pragma unroll
    for (int i = 0; i < 8; i++) {
        float w = inv_v * s_lwv[i];
        #pragma unroll
        for (int c = 0; c < 3; c++) vn[i*3 + c] = g_Vout[ge*24 + i*3 + c] * w;
    }
    #pragma unroll
    for (int o = 0; o < 8; o++) {
        #pragma unroll
        for (int c = 0; c < 3; c++) {
            float a = 0.f;
            #pragma unroll
            for (int i = 0; i < 8; i++) a += vn[i*3 + c] * s_ev[i*8 + o];
            out[ge*40 + 16 + o*3 + c] = a;
        }
    }
}

// ======================================================================
extern "C" void kernel_launch(void* const* d_in, const int* in_sizes, int n_in,
                              void* d_out, int out_size)
{
    const float* node_fea  = (const float*)d_in[0];
    const float* edge_attr = (const float*)d_in[1];
    const int*   edge_index= (const int*)  d_in[2];
    const int*   xs        = (const int*)  d_in[3];
    const int*   batch     = (const int*)  d_in[4];
    const float* w_rh      = (const float*)d_in[5];
    const float* b_rh      = (const float*)d_in[6];
    const float* w_ro      = (const float*)d_in[7];
    const float* b_ro      = (const float*)d_in[8];
    const float* w_pre     = (const float*)d_in[9];
    const float* b_pre     = (const float*)d_in[10];
    const float* w_sc      = (const float*)d_in[11];
    const float* w_post_s  = (const float*)d_in[12];
    const float* b_post_s  = (const float*)d_in[13];
    const float* w_post_v  = (const float*)d_in[14];
    const float* ln_w_s    = (const float*)d_in[15];
    const float* ln_b_s    = (const float*)d_in[16];
    const float* ln_w_v    = (const float*)d_in[17];
    const float* w_skip    = (const float*)d_in[18];
    const float* w_edge_s  = (const float*)d_in[19];
    const float* b_edge_s  = (const float*)d_in[20];
    const float* w_edge_v  = (const float*)d_in[21];
    float* out = (float*)d_out;

    cudaFuncSetAttribute(k_main, cudaFuncAttributeMaxDynamicSharedMemorySize, SMEM_BYTES);

    k_zero<<<1, 288>>>();
    k_prep<<<240, 256>>>(w_ro);
    k_main<<<EDGES/TE, NT, SMEM_BYTES>>>(
        node_fea, edge_attr, edge_index, xs, batch,
        w_rh, b_rh, w_ro, b_ro, w_pre, b_pre, w_sc,
        w_post_s, b_post_s, w_post_v);
    k_stats<<<1, 256>>>();
    k_final<<<EDGES/256, 256>>>(
        edge_attr, edge_index, batch,
        ln_w_s, ln_b_s, ln_w_v, w_skip, w_edge_s, b_edge_s, w_edge_v, out);
}